// round 1
// baseline (speedup 1.0000x reference)
#include <cuda_runtime.h>
#include <cstdint>

// ---------------------------------------------------------------------------
// Experts MoE: per-expert  X[2048x2048] @ W1[2048x2816] -> swiglu -> act[2048x1408]
//                          act @ W2[1408x2048] -> out
// 8 experts, equal token split (static per reference).
// Round 1: tf32 mma.sync baseline, 2 kernels, device-global intermediate.
// ---------------------------------------------------------------------------

#define NEXPERTS 8
#define TOK_E    2048      // tokens per expert
#define HID      2048
#define FFN      1408
#define FFN2     2816

// 92.3 MB scratch for swiglu activations (allowed: __device__ global)
__device__ float g_act[(size_t)NEXPERTS * TOK_E * FFN];

__device__ __forceinline__ float f2tf32(float x) {
    uint32_t r;
    asm("cvt.rna.tf32.f32 %0, %1;" : "=r"(r) : "f"(x));
    return __uint_as_float(r);
}

__device__ __forceinline__ float4 cvt4(float4 v) {
    float4 r;
    r.x = f2tf32(v.x); r.y = f2tf32(v.y); r.z = f2tf32(v.z); r.w = f2tf32(v.w);
    return r;
}

__device__ __forceinline__ void mma8(float d[4], const uint32_t a[4], const uint32_t b[2]) {
    asm volatile(
        "mma.sync.aligned.m16n8k8.row.col.f32.tf32.tf32.f32 "
        "{%0,%1,%2,%3}, {%4,%5,%6,%7}, {%8,%9}, {%0,%1,%2,%3};\n"
        : "+f"(d[0]), "+f"(d[1]), "+f"(d[2]), "+f"(d[3])
        : "r"(a[0]), "r"(a[1]), "r"(a[2]), "r"(a[3]), "r"(b[0]), "r"(b[1]));
}

__device__ __forceinline__ float silu(float x) {
    return x / (1.0f + __expf(-x));
}

// ===========================================================================
// Kernel 1: GEMM1 + swiglu.
// Block tile: M=128 rows x 64 act-columns. Computes BOTH the "a" half
// (cols [n, n+64) of W1) and the "b" half (cols [n+1408, n+1408+64)), then
// writes act = silu(a)*b.
// 256 threads = 8 warps laid out 4(m) x 2(n). Warp tile 32x32 per half.
// BK = 32, double-buffered smem.
// ===========================================================================

#define K1_BM 128
#define K1_BN 64
#define K1_BK 32
#define K1_AS 36      // A smem row stride (floats), padded
#define K1_BS 68      // B smem row stride (floats), padded
#define K1_ABUF (K1_BM * K1_AS)            // 4608 floats per buffer
#define K1_BBUF (2 * K1_BK * K1_BS)        // 4352 floats per buffer (2 halves)

__global__ __launch_bounds__(256)
void gemm1_swiglu_kernel(const float* __restrict__ X, const float* __restrict__ W1) {
    const int e     = blockIdx.z;
    const int mtile = blockIdx.y;   // 0..15
    const int ntile = blockIdx.x;   // 0..21
    const int tid   = threadIdx.x;
    const int warp  = tid >> 5;
    const int lane  = tid & 31;
    const int wm    = warp >> 1;    // 0..3
    const int wn    = warp & 1;     // 0..1
    const int lg    = lane >> 2;    // group id 0..7
    const int lt    = lane & 3;     // thread in group 0..3

    extern __shared__ float smem[];
    float* As = smem;                     // [2][K1_ABUF]
    float* Bs = smem + 2 * K1_ABUF;       // [2][K1_BBUF]

    const float* Xe  = X  + ((size_t)e * TOK_E + (size_t)mtile * K1_BM) * HID;
    const float* W1e = W1 + (size_t)e * HID * FFN2;
    const int ncol0  = ntile * K1_BN;

    float acc[2][2][4][4];   // [half][mtileW][ntileW][frag]
    #pragma unroll
    for (int h = 0; h < 2; h++)
        #pragma unroll
        for (int i = 0; i < 2; i++)
            #pragma unroll
            for (int j = 0; j < 4; j++)
                #pragma unroll
                for (int r = 0; r < 4; r++) acc[h][i][j][r] = 0.0f;

    float4 aReg[4], bReg[4];

    auto loadA = [&](int kt) {
        const int k0 = kt * K1_BK;
        #pragma unroll
        for (int i = 0; i < 4; i++) {
            int idx = tid + i * 256;           // 0..1023
            int row = idx >> 3;                // 0..127
            int c   = (idx & 7) << 2;          // 0..28
            aReg[i] = *reinterpret_cast<const float4*>(Xe + (size_t)row * HID + k0 + c);
        }
    };
    auto loadB = [&](int kt) {
        const int k0 = kt * K1_BK;
        #pragma unroll
        for (int i = 0; i < 4; i++) {
            int idx  = tid + i * 256;          // 0..1023
            int half = idx >> 9;               // 0..1
            int rem  = idx & 511;
            int k    = rem >> 4;               // 0..31
            int c    = (rem & 15) << 2;        // 0..60
            bReg[i] = *reinterpret_cast<const float4*>(
                W1e + (size_t)(k0 + k) * FFN2 + half * FFN + ncol0 + c);
        }
    };
    auto storeA = [&](int buf) {
        float* dst = As + buf * K1_ABUF;
        #pragma unroll
        for (int i = 0; i < 4; i++) {
            int idx = tid + i * 256;
            int row = idx >> 3;
            int c   = (idx & 7) << 2;
            *reinterpret_cast<float4*>(dst + row * K1_AS + c) = cvt4(aReg[i]);
        }
    };
    auto storeB = [&](int buf) {
        float* dst = Bs + buf * K1_BBUF;
        #pragma unroll
        for (int i = 0; i < 4; i++) {
            int idx  = tid + i * 256;
            int half = idx >> 9;
            int rem  = idx & 511;
            int k    = rem >> 4;
            int c    = (rem & 15) << 2;
            *reinterpret_cast<float4*>(dst + (half * K1_BK + k) * K1_BS + c) = cvt4(bReg[i]);
        }
    };
    auto compute = [&](int buf) {
        const float* A = As + buf * K1_ABUF;
        const float* B = Bs + buf * K1_BBUF;
        #pragma unroll
        for (int ks = 0; ks < 4; ks++) {
            const int k0 = ks * 8;
            uint32_t af[2][4];
            #pragma unroll
            for (int mt = 0; mt < 2; mt++) {
                const float* Ab = A + (wm * 32 + mt * 16 + lg) * K1_AS + k0 + lt;
                af[mt][0] = __float_as_uint(Ab[0]);
                af[mt][1] = __float_as_uint(Ab[8 * K1_AS]);
                af[mt][2] = __float_as_uint(Ab[4]);
                af[mt][3] = __float_as_uint(Ab[8 * K1_AS + 4]);
            }
            #pragma unroll
            for (int h = 0; h < 2; h++) {
                #pragma unroll
                for (int nt = 0; nt < 4; nt++) {
                    const float* Bb = B + (h * K1_BK + k0 + lt) * K1_BS + wn * 32 + nt * 8 + lg;
                    uint32_t bf[2];
                    bf[0] = __float_as_uint(Bb[0]);
                    bf[1] = __float_as_uint(Bb[4 * K1_BS]);
                    mma8(acc[h][0][nt], af[0], bf);
                    mma8(acc[h][1][nt], af[1], bf);
                }
            }
        }
    };

    // ---- main loop: double buffered ----
    loadA(0); loadB(0);
    storeA(0); storeB(0);
    __syncthreads();

    const int NT = HID / K1_BK;  // 64
    for (int t = 0; t < NT; t++) {
        const int buf = t & 1;
        if (t + 1 < NT) { loadA(t + 1); loadB(t + 1); }
        compute(buf);
        if (t + 1 < NT) { storeA(buf ^ 1); storeB(buf ^ 1); }
        __syncthreads();
    }

    // ---- epilogue: swiglu + store ----
    float* actOut = g_act + ((size_t)e * TOK_E + (size_t)mtile * K1_BM) * FFN + ncol0;
    #pragma unroll
    for (int mt = 0; mt < 2; mt++) {
        #pragma unroll
        for (int nt = 0; nt < 4; nt++) {
            const int r = wm * 32 + mt * 16 + lg;
            const int c = wn * 32 + nt * 8 + 2 * lt;
            const float* a = acc[0][mt][nt];
            const float* b = acc[1][mt][nt];
            float2 v0 = make_float2(silu(a[0]) * b[0], silu(a[1]) * b[1]);
            float2 v1 = make_float2(silu(a[2]) * b[2], silu(a[3]) * b[3]);
            *reinterpret_cast<float2*>(actOut + (size_t)r * FFN + c)       = v0;
            *reinterpret_cast<float2*>(actOut + (size_t)(r + 8) * FFN + c) = v1;
        }
    }
}

// ===========================================================================
// Kernel 2: GEMM2. out[2048x2048] = act[2048x1408] @ W2[1408x2048] per expert.
// Block tile 128x128, BK=32, 8 warps 4(m) x 2(n), warp tile 32x64.
// ===========================================================================

#define K2_BM 128
#define K2_BN 128
#define K2_BK 32
#define K2_AS 36
#define K2_BS 132
#define K2_ABUF (K2_BM * K2_AS)
#define K2_BBUF (K2_BK * K2_BS)

__global__ __launch_bounds__(256)
void gemm2_kernel(const float* __restrict__ W2, float* __restrict__ out) {
    const int e     = blockIdx.z;
    const int mtile = blockIdx.y;   // 0..15
    const int ntile = blockIdx.x;   // 0..15
    const int tid   = threadIdx.x;
    const int warp  = tid >> 5;
    const int lane  = tid & 31;
    const int wm    = warp >> 1;
    const int wn    = warp & 1;
    const int lg    = lane >> 2;
    const int lt    = lane & 3;

    extern __shared__ float smem[];
    float* As = smem;
    float* Bs = smem + 2 * K2_ABUF;

    const float* Ae  = g_act + ((size_t)e * TOK_E + (size_t)mtile * K2_BM) * FFN;
    const float* W2e = W2 + (size_t)e * FFN * HID;
    const int ncol0  = ntile * K2_BN;

    float acc[2][8][4];
    #pragma unroll
    for (int i = 0; i < 2; i++)
        #pragma unroll
        for (int j = 0; j < 8; j++)
            #pragma unroll
            for (int r = 0; r < 4; r++) acc[i][j][r] = 0.0f;

    float4 aReg[4], bReg[4];

    auto loadA = [&](int kt) {
        const int k0 = kt * K2_BK;
        #pragma unroll
        for (int i = 0; i < 4; i++) {
            int idx = tid + i * 256;
            int row = idx >> 3;
            int c   = (idx & 7) << 2;
            aReg[i] = *reinterpret_cast<const float4*>(Ae + (size_t)row * FFN + k0 + c);
        }
    };
    auto loadB = [&](int kt) {
        const int k0 = kt * K2_BK;
        #pragma unroll
        for (int i = 0; i < 4; i++) {
            int idx = tid + i * 256;          // 0..1023
            int k   = idx >> 5;               // 0..31
            int c   = (idx & 31) << 2;        // 0..124
            bReg[i] = *reinterpret_cast<const float4*>(W2e + (size_t)(k0 + k) * HID + ncol0 + c);
        }
    };
    auto storeA = [&](int buf) {
        float* dst = As + buf * K2_ABUF;
        #pragma unroll
        for (int i = 0; i < 4; i++) {
            int idx = tid + i * 256;
            int row = idx >> 3;
            int c   = (idx & 7) << 2;
            *reinterpret_cast<float4*>(dst + row * K2_AS + c) = cvt4(aReg[i]);
        }
    };
    auto storeB = [&](int buf) {
        float* dst = Bs + buf * K2_BBUF;
        #pragma unroll
        for (int i = 0; i < 4; i++) {
            int idx = tid + i * 256;
            int k   = idx >> 5;
            int c   = (idx & 31) << 2;
            *reinterpret_cast<float4*>(dst + k * K2_BS + c) = cvt4(bReg[i]);
        }
    };
    auto compute = [&](int buf) {
        const float* A = As + buf * K2_ABUF;
        const float* B = Bs + buf * K2_BBUF;
        #pragma unroll
        for (int ks = 0; ks < 4; ks++) {
            const int k0 = ks * 8;
            uint32_t af[2][4];
            #pragma unroll
            for (int mt = 0; mt < 2; mt++) {
                const float* Ab = A + (wm * 32 + mt * 16 + lg) * K2_AS + k0 + lt;
                af[mt][0] = __float_as_uint(Ab[0]);
                af[mt][1] = __float_as_uint(Ab[8 * K2_AS]);
                af[mt][2] = __float_as_uint(Ab[4]);
                af[mt][3] = __float_as_uint(Ab[8 * K2_AS + 4]);
            }
            #pragma unroll
            for (int nt = 0; nt < 8; nt++) {
                const float* Bb = B + (k0 + lt) * K2_BS + wn * 64 + nt * 8 + lg;
                uint32_t bf[2];
                bf[0] = __float_as_uint(Bb[0]);
                bf[1] = __float_as_uint(Bb[4 * K2_BS]);
                mma8(acc[0][nt], af[0], bf);
                mma8(acc[1][nt], af[1], bf);
            }
        }
    };

    loadA(0); loadB(0);
    storeA(0); storeB(0);
    __syncthreads();

    const int NT = FFN / K2_BK;  // 44
    for (int t = 0; t < NT; t++) {
        const int buf = t & 1;
        if (t + 1 < NT) { loadA(t + 1); loadB(t + 1); }
        compute(buf);
        if (t + 1 < NT) { storeA(buf ^ 1); storeB(buf ^ 1); }
        __syncthreads();
    }

    float* outP = out + ((size_t)e * TOK_E + (size_t)mtile * K2_BM) * HID + ncol0;
    #pragma unroll
    for (int mt = 0; mt < 2; mt++) {
        #pragma unroll
        for (int nt = 0; nt < 8; nt++) {
            const int r = wm * 32 + mt * 16 + lg;
            const int c = wn * 64 + nt * 8 + 2 * lt;
            const float* d = acc[mt][nt];
            *reinterpret_cast<float2*>(outP + (size_t)r * HID + c)       = make_float2(d[0], d[1]);
            *reinterpret_cast<float2*>(outP + (size_t)(r + 8) * HID + c) = make_float2(d[2], d[3]);
        }
    }
}

// ===========================================================================
// Launch
// ===========================================================================

extern "C" void kernel_launch(void* const* d_in, const int* in_sizes, int n_in,
                              void* d_out, int out_size) {
    const float* X  = (const float*)d_in[0];
    // d_in[1] = num_tokens_per_expert (int64) -- equal static split per reference; unused
    const float* W1 = (const float*)d_in[2];
    const float* W2 = (const float*)d_in[3];
    float* out = (float*)d_out;

    const int smem1 = (2 * K1_ABUF + 2 * K1_BBUF) * sizeof(float);  // ~71.7 KB
    const int smem2 = (2 * K2_ABUF + 2 * K2_BBUF) * sizeof(float);  // ~70.7 KB
    cudaFuncSetAttribute(gemm1_swiglu_kernel, cudaFuncAttributeMaxDynamicSharedMemorySize, smem1);
    cudaFuncSetAttribute(gemm2_kernel,        cudaFuncAttributeMaxDynamicSharedMemorySize, smem2);

    dim3 grid1(FFN / K1_BN, TOK_E / K1_BM, NEXPERTS);   // 22 x 16 x 8
    dim3 grid2(HID / K2_BN, TOK_E / K2_BM, NEXPERTS);   // 16 x 16 x 8
    gemm1_swiglu_kernel<<<grid1, 256, smem1>>>(X, W1);
    gemm2_kernel<<<grid2, 256, smem2>>>(W2, out);
}

// round 3
// speedup vs baseline: 1.1578x; 1.1578x over previous
#include <cuda_runtime.h>
#include <cstdint>

// ---------------------------------------------------------------------------
// Experts MoE, mma.sync tf32 (compute_103-safe: NO arch-'a' instructions).
// Round 3: ldmatrix.x4-fed fragments, B smem transposed to [n][k] k-major.
// GEMM1: X[2048x2048] @ W1[2048x2816] -> swiglu -> act[2048x1408] per expert
// GEMM2: act @ W2[1408x2048] -> out
// ---------------------------------------------------------------------------

#define NEXPERTS 8
#define TOK_E    2048
#define HID      2048
#define FFN      1408
#define FFN2     2816

// strides in floats (pad 36 -> conflict-free STS.128 / LDSM for row-mapped lanes)
#define RS 36

// GEMM1: block 128m x (64+64)n halves, 8 warps 4(m)x2(n), warp 32x32 per half
#define K1_BM 128
#define K1_BN 64
#define K1_ABUF (128 * RS)     // 4608 floats
#define K1_BBUF (128 * RS)     // 128 rows (64 a-half + 64 b-half) x 32k

// GEMM2: block 128m x 128n, 8 warps 4(m)x2(n), warp 32x64
#define K2_BM 128
#define K2_BN 128
#define K2_ABUF (128 * RS)
#define K2_BBUF (128 * RS)

#define BK 32

__device__ float g_act[(size_t)NEXPERTS * TOK_E * FFN];

__device__ __forceinline__ uint32_t s2u(const void* p) {
    uint32_t a;
    asm("{ .reg .u64 t; cvta.to.shared.u64 t, %1; cvt.u32.u64 %0, t; }" : "=r"(a) : "l"(p));
    return a;
}
__device__ __forceinline__ uint32_t f2tf32(float x) {
    uint32_t r;
    asm("cvt.rna.tf32.f32 %0, %1;" : "=r"(r) : "f"(x));
    return r;
}
__device__ __forceinline__ void mma8(float d[4], const uint32_t a[4], uint32_t b0, uint32_t b1) {
    asm volatile(
        "mma.sync.aligned.m16n8k8.row.col.f32.tf32.tf32.f32 "
        "{%0,%1,%2,%3}, {%4,%5,%6,%7}, {%8,%9}, {%0,%1,%2,%3};\n"
        : "+f"(d[0]), "+f"(d[1]), "+f"(d[2]), "+f"(d[3])
        : "r"(a[0]), "r"(a[1]), "r"(a[2]), "r"(a[3]), "r"(b0), "r"(b1));
}
__device__ __forceinline__ void ldsm4(uint32_t& r0, uint32_t& r1, uint32_t& r2, uint32_t& r3,
                                      uint32_t addr) {
    asm volatile("ldmatrix.sync.aligned.m8n8.x4.shared.b16 {%0,%1,%2,%3}, [%4];"
                 : "=r"(r0), "=r"(r1), "=r"(r2), "=r"(r3) : "r"(addr));
}
__device__ __forceinline__ float silu(float x) { return x / (1.0f + __expf(-x)); }

// ===========================================================================
// GEMM1 + swiglu
// ===========================================================================
__global__ __launch_bounds__(256)
void gemm1_swiglu_kernel(const float* __restrict__ X, const float* __restrict__ W1) {
    const int e     = blockIdx.z;
    const int mtile = blockIdx.y;
    const int ntile = blockIdx.x;
    const int tid   = threadIdx.x;
    const int warp  = tid >> 5;
    const int lane  = tid & 31;
    const int wm    = warp >> 1;
    const int wn    = warp & 1;
    const int lg    = lane >> 2;
    const int lt    = lane & 3;

    extern __shared__ float smem[];
    float* As = smem;                    // [2][K1_ABUF]  layout [m][k], k-major
    float* Bs = smem + 2 * K1_ABUF;      // [2][K1_BBUF]  layout [nrow][k], k-major

    const float* Xe  = X  + ((size_t)e * TOK_E + (size_t)mtile * K1_BM) * HID;
    const float* W1e = W1 + (size_t)e * HID * FFN2;
    const int n0     = ntile * K1_BN;

    // B producer: thread -> one n-row, half of k
    const int  bRow   = tid & 127;                 // 0..127 (0-63 a-half, 64-127 b-half)
    const int  bKh    = (tid >> 7) * 16;           // 0 or 16
    const int  bCol   = (bRow < 64) ? (n0 + bRow) : (FFN + n0 + (bRow - 64));
    const float* gBc  = W1e + bCol;

    // LDSM per-lane byte offsets (stride RS floats = 144B)
    const uint32_t sbA = s2u(As);
    const uint32_t sbB = s2u(Bs);
    const uint32_t offA = (uint32_t)((lane & 15) * RS * 4 + (lane >> 4) * 16);
    const uint32_t offB = (uint32_t)((((lane >> 4) & 1) * 8 + (lane & 7)) * RS * 4
                                     + ((lane >> 3) & 1) * 16);

    float acc[2][2][4][4];
    #pragma unroll
    for (int h = 0; h < 2; h++)
        #pragma unroll
        for (int i = 0; i < 2; i++)
            #pragma unroll
            for (int j = 0; j < 4; j++)
                #pragma unroll
                for (int r = 0; r < 4; r++) acc[h][i][j][r] = 0.0f;

    float4 aPre[4];
    float  bPre[16];

    auto ldgA = [&](int kt) {
        const int k0 = kt * BK;
        #pragma unroll
        for (int i = 0; i < 4; i++) {
            int idx = tid + i * 256;
            int row = idx >> 3;
            int c   = (idx & 7) << 2;
            aPre[i] = *reinterpret_cast<const float4*>(Xe + (size_t)row * HID + k0 + c);
        }
    };
    auto ldgB = [&](int kt) {
        const size_t k0 = (size_t)(kt * BK + bKh);
        #pragma unroll
        for (int j = 0; j < 16; j++) bPre[j] = gBc[(k0 + j) * FFN2];
    };
    auto stsA = [&](int buf) {
        float* dst = As + buf * K1_ABUF;
        #pragma unroll
        for (int i = 0; i < 4; i++) {
            int idx = tid + i * 256;
            int row = idx >> 3;
            int c   = (idx & 7) << 2;
            uint4 v;
            v.x = f2tf32(aPre[i].x); v.y = f2tf32(aPre[i].y);
            v.z = f2tf32(aPre[i].z); v.w = f2tf32(aPre[i].w);
            *reinterpret_cast<uint4*>(dst + row * RS + c) = v;
        }
    };
    auto stsB = [&](int buf) {
        float* dst = Bs + buf * K1_BBUF + bRow * RS + bKh;
        #pragma unroll
        for (int i = 0; i < 4; i++) {
            uint4 v;
            v.x = f2tf32(bPre[4*i+0]); v.y = f2tf32(bPre[4*i+1]);
            v.z = f2tf32(bPre[4*i+2]); v.w = f2tf32(bPre[4*i+3]);
            *reinterpret_cast<uint4*>(dst + 4 * i) = v;
        }
    };
    auto compute = [&](int buf) {
        const uint32_t aB = sbA + (uint32_t)buf * K1_ABUF * 4;
        const uint32_t bB = sbB + (uint32_t)buf * K1_BBUF * 4;
        #pragma unroll
        for (int ks = 0; ks < 4; ks++) {
            const uint32_t kOff = (uint32_t)ks * 32;   // 8 floats
            uint32_t af[2][4];
            #pragma unroll
            for (int mt = 0; mt < 2; mt++)
                ldsm4(af[mt][0], af[mt][1], af[mt][2], af[mt][3],
                      aB + (uint32_t)((wm * 32 + mt * 16) * RS * 4) + kOff + offA);
            #pragma unroll
            for (int h = 0; h < 2; h++) {
                #pragma unroll
                for (int np = 0; np < 2; np++) {
                    uint32_t b0, b1, b2, b3;
                    ldsm4(b0, b1, b2, b3,
                          bB + (uint32_t)((h * 64 + wn * 32 + np * 16) * RS * 4) + kOff + offB);
                    mma8(acc[h][0][np*2+0], af[0], b0, b1);
                    mma8(acc[h][1][np*2+0], af[1], b0, b1);
                    mma8(acc[h][0][np*2+1], af[0], b2, b3);
                    mma8(acc[h][1][np*2+1], af[1], b2, b3);
                }
            }
        }
    };

    ldgA(0); ldgB(0);
    stsA(0); stsB(0);
    __syncthreads();

    const int NT = HID / BK;   // 64
    for (int t = 0; t < NT; t++) {
        const int buf = t & 1;
        if (t + 1 < NT) { ldgA(t + 1); ldgB(t + 1); }
        compute(buf);
        if (t + 1 < NT) { stsA(buf ^ 1); stsB(buf ^ 1); }
        __syncthreads();
    }

    float* actOut = g_act + ((size_t)e * TOK_E + (size_t)mtile * K1_BM) * FFN + n0;
    #pragma unroll
    for (int mt = 0; mt < 2; mt++) {
        #pragma unroll
        for (int nt = 0; nt < 4; nt++) {
            const int r = wm * 32 + mt * 16 + lg;
            const int c = wn * 32 + nt * 8 + 2 * lt;
            const float* a = acc[0][mt][nt];
            const float* b = acc[1][mt][nt];
            float2 v0 = make_float2(silu(a[0]) * b[0], silu(a[1]) * b[1]);
            float2 v1 = make_float2(silu(a[2]) * b[2], silu(a[3]) * b[3]);
            *reinterpret_cast<float2*>(actOut + (size_t)r * FFN + c)       = v0;
            *reinterpret_cast<float2*>(actOut + (size_t)(r + 8) * FFN + c) = v1;
        }
    }
}

// ===========================================================================
// GEMM2
// ===========================================================================
__global__ __launch_bounds__(256)
void gemm2_kernel(const float* __restrict__ W2, float* __restrict__ out) {
    const int e     = blockIdx.z;
    const int mtile = blockIdx.y;
    const int ntile = blockIdx.x;
    const int tid   = threadIdx.x;
    const int warp  = tid >> 5;
    const int lane  = tid & 31;
    const int wm    = warp >> 1;
    const int wn    = warp & 1;
    const int lg    = lane >> 2;
    const int lt    = lane & 3;

    extern __shared__ float smem[];
    float* As = smem;
    float* Bs = smem + 2 * K2_ABUF;

    const float* Ae  = g_act + ((size_t)e * TOK_E + (size_t)mtile * K2_BM) * FFN;
    const float* W2e = W2 + (size_t)e * FFN * HID;
    const int n0     = ntile * K2_BN;

    const int  bRow  = tid & 127;
    const int  bKh   = (tid >> 7) * 16;
    const float* gBc = W2e + n0 + bRow;

    const uint32_t sbA = s2u(As);
    const uint32_t sbB = s2u(Bs);
    const uint32_t offA = (uint32_t)((lane & 15) * RS * 4 + (lane >> 4) * 16);
    const uint32_t offB = (uint32_t)((((lane >> 4) & 1) * 8 + (lane & 7)) * RS * 4
                                     + ((lane >> 3) & 1) * 16);

    float acc[2][8][4];
    #pragma unroll
    for (int i = 0; i < 2; i++)
        #pragma unroll
        for (int j = 0; j < 8; j++)
            #pragma unroll
            for (int r = 0; r < 4; r++) acc[i][j][r] = 0.0f;

    float4 aPre[4];
    float  bPre[16];

    auto ldgA = [&](int kt) {
        const int k0 = kt * BK;
        #pragma unroll
        for (int i = 0; i < 4; i++) {
            int idx = tid + i * 256;
            int row = idx >> 3;
            int c   = (idx & 7) << 2;
            aPre[i] = *reinterpret_cast<const float4*>(Ae + (size_t)row * FFN + k0 + c);
        }
    };
    auto ldgB = [&](int kt) {
        const size_t k0 = (size_t)(kt * BK + bKh);
        #pragma unroll
        for (int j = 0; j < 16; j++) bPre[j] = gBc[(k0 + j) * HID];
    };
    auto stsA = [&](int buf) {
        float* dst = As + buf * K2_ABUF;
        #pragma unroll
        for (int i = 0; i < 4; i++) {
            int idx = tid + i * 256;
            int row = idx >> 3;
            int c   = (idx & 7) << 2;
            uint4 v;
            v.x = f2tf32(aPre[i].x); v.y = f2tf32(aPre[i].y);
            v.z = f2tf32(aPre[i].z); v.w = f2tf32(aPre[i].w);
            *reinterpret_cast<uint4*>(dst + row * RS + c) = v;
        }
    };
    auto stsB = [&](int buf) {
        float* dst = Bs + buf * K2_BBUF + bRow * RS + bKh;
        #pragma unroll
        for (int i = 0; i < 4; i++) {
            uint4 v;
            v.x = f2tf32(bPre[4*i+0]); v.y = f2tf32(bPre[4*i+1]);
            v.z = f2tf32(bPre[4*i+2]); v.w = f2tf32(bPre[4*i+3]);
            *reinterpret_cast<uint4*>(dst + 4 * i) = v;
        }
    };
    auto compute = [&](int buf) {
        const uint32_t aB = sbA + (uint32_t)buf * K2_ABUF * 4;
        const uint32_t bB = sbB + (uint32_t)buf * K2_BBUF * 4;
        #pragma unroll
        for (int ks = 0; ks < 4; ks++) {
            const uint32_t kOff = (uint32_t)ks * 32;
            uint32_t af[2][4];
            #pragma unroll
            for (int mt = 0; mt < 2; mt++)
                ldsm4(af[mt][0], af[mt][1], af[mt][2], af[mt][3],
                      aB + (uint32_t)((wm * 32 + mt * 16) * RS * 4) + kOff + offA);
            #pragma unroll
            for (int np = 0; np < 4; np++) {
                uint32_t b0, b1, b2, b3;
                ldsm4(b0, b1, b2, b3,
                      bB + (uint32_t)((wn * 64 + np * 16) * RS * 4) + kOff + offB);
                mma8(acc[0][np*2+0], af[0], b0, b1);
                mma8(acc[1][np*2+0], af[1], b0, b1);
                mma8(acc[0][np*2+1], af[0], b2, b3);
                mma8(acc[1][np*2+1], af[1], b2, b3);
            }
        }
    };

    ldgA(0); ldgB(0);
    stsA(0); stsB(0);
    __syncthreads();

    const int NT = FFN / BK;   // 44
    for (int t = 0; t < NT; t++) {
        const int buf = t & 1;
        if (t + 1 < NT) { ldgA(t + 1); ldgB(t + 1); }
        compute(buf);
        if (t + 1 < NT) { stsA(buf ^ 1); stsB(buf ^ 1); }
        __syncthreads();
    }

    float* outP = out + ((size_t)e * TOK_E + (size_t)mtile * K2_BM) * HID + n0;
    #pragma unroll
    for (int mt = 0; mt < 2; mt++) {
        #pragma unroll
        for (int nt = 0; nt < 8; nt++) {
            const int r = wm * 32 + mt * 16 + lg;
            const int c = wn * 64 + nt * 8 + 2 * lt;
            const float* d = acc[mt][nt];
            *reinterpret_cast<float2*>(outP + (size_t)r * HID + c)       = make_float2(d[0], d[1]);
            *reinterpret_cast<float2*>(outP + (size_t)(r + 8) * HID + c) = make_float2(d[2], d[3]);
        }
    }
}

// ===========================================================================
// Launch
// ===========================================================================
extern "C" void kernel_launch(void* const* d_in, const int* in_sizes, int n_in,
                              void* d_out, int out_size) {
    const float* X  = (const float*)d_in[0];
    const float* W1 = (const float*)d_in[2];
    const float* W2 = (const float*)d_in[3];
    float* out = (float*)d_out;

    const int smem1 = (2 * K1_ABUF + 2 * K1_BBUF) * sizeof(float);  // 73728
    const int smem2 = (2 * K2_ABUF + 2 * K2_BBUF) * sizeof(float);  // 73728
    cudaFuncSetAttribute(gemm1_swiglu_kernel, cudaFuncAttributeMaxDynamicSharedMemorySize, smem1);
    cudaFuncSetAttribute(gemm2_kernel,        cudaFuncAttributeMaxDynamicSharedMemorySize, smem2);

    dim3 grid1(FFN / K1_BN, TOK_E / K1_BM, NEXPERTS);   // 22 x 16 x 8
    dim3 grid2(HID / K2_BN, TOK_E / K2_BM, NEXPERTS);   // 16 x 16 x 8
    gemm1_swiglu_kernel<<<grid1, 256, smem1>>>(X, W1);
    gemm2_kernel<<<grid2, 256, smem2>>>(W2, out);
}

// round 4
// speedup vs baseline: 1.4886x; 1.2857x over previous
#include <cuda_runtime.h>
#include <cuda_fp16.h>
#include <cstdint>

// ---------------------------------------------------------------------------
// Experts MoE, fp16 mma.sync m16n8k16 (compute_103-safe), fp32 accum.
// Pre-pass: X -> fp16; W1,W2 -> transposed [n][k] fp16.
// GEMM1: Xh @ W1 -> swiglu -> acth (fp16).  GEMM2: acth @ W2 -> out (f32).
// 128x256 block, 8 warps (2m x 4n) of 64x64, BK=64, 3-stage cp.async.
// ---------------------------------------------------------------------------

#define NEXPERTS 8
#define TOK_E    2048
#define HID      2048
#define FFN      1408
#define FFN2     2816

#define RSB 144                 // smem row stride bytes (72 fp16) - conflict free
#define A_STG (128 * RSB)       // 18432
#define B_STG (256 * RSB)       // 36864
#define STG   (A_STG + B_STG)   // 55296
#define SMEM_TOTAL (3 * STG)    // 165888

__device__ __half g_Xh [(size_t)TOK_E * NEXPERTS * HID];
__device__ __half g_W1t[(size_t)NEXPERTS * FFN2 * HID];    // [e][n][k]
__device__ __half g_W2t[(size_t)NEXPERTS * HID * FFN];     // [e][n][k]
__device__ __half g_act[(size_t)NEXPERTS * TOK_E * FFN];

__device__ __forceinline__ uint32_t s2u(const void* p) {
    uint32_t a;
    asm("{ .reg .u64 t; cvta.to.shared.u64 t, %1; cvt.u32.u64 %0, t; }" : "=r"(a) : "l"(p));
    return a;
}
__device__ __forceinline__ void cpa16(uint32_t s, const void* g) {
    asm volatile("cp.async.cg.shared.global [%0], [%1], 16;" :: "r"(s), "l"(g));
}
__device__ __forceinline__ void cp_commit() {
    asm volatile("cp.async.commit_group;" ::: "memory");
}
__device__ __forceinline__ void cp_wait1() {
    asm volatile("cp.async.wait_group 1;" ::: "memory");
}
__device__ __forceinline__ void ldsm4(uint32_t& r0, uint32_t& r1, uint32_t& r2, uint32_t& r3,
                                      uint32_t addr) {
    asm volatile("ldmatrix.sync.aligned.m8n8.x4.shared.b16 {%0,%1,%2,%3}, [%4];"
                 : "=r"(r0), "=r"(r1), "=r"(r2), "=r"(r3) : "r"(addr));
}
__device__ __forceinline__ void mma16(float d[4], const uint32_t a[4], uint32_t b0, uint32_t b1) {
    asm volatile(
        "mma.sync.aligned.m16n8k16.row.col.f32.f16.f16.f32 "
        "{%0,%1,%2,%3}, {%4,%5,%6,%7}, {%8,%9}, {%0,%1,%2,%3};\n"
        : "+f"(d[0]), "+f"(d[1]), "+f"(d[2]), "+f"(d[3])
        : "r"(a[0]), "r"(a[1]), "r"(a[2]), "r"(a[3]), "r"(b0), "r"(b1));
}
__device__ __forceinline__ float silu(float x) { return x / (1.0f + __expf(-x)); }

// ===========================================================================
// Pre-pass kernels
// ===========================================================================
__global__ __launch_bounds__(256)
void cvt_x_kernel(const float* __restrict__ X) {
    size_t i = (size_t)blockIdx.x * blockDim.x + threadIdx.x;   // float4 index
    float4 v = reinterpret_cast<const float4*>(X)[i];
    __half2* o = reinterpret_cast<__half2*>(g_Xh) + 2 * i;
    o[0] = __floats2half2_rn(v.x, v.y);
    o[1] = __floats2half2_rn(v.z, v.w);
}

// in: [E][R][C] f32 row-major  ->  out: [E][C][R] fp16
__global__ __launch_bounds__(256)
void transpose_cvt_kernel(const float* __restrict__ in, __half* __restrict__ out,
                          int R, int C) {
    __shared__ float tile[32][33];
    const size_t eo = (size_t)blockIdx.z * R * C;
    const int r0 = blockIdx.y * 32, c0 = blockIdx.x * 32;
    const int tx = threadIdx.x & 31, ty = threadIdx.x >> 5;   // 32 x 8
    #pragma unroll
    for (int j = 0; j < 32; j += 8)
        tile[ty + j][tx] = in[eo + (size_t)(r0 + ty + j) * C + c0 + tx];
    __syncthreads();
    #pragma unroll
    for (int j = 0; j < 32; j += 8)
        out[eo + (size_t)(c0 + ty + j) * R + r0 + tx] = __float2half_rn(tile[tx][ty + j]);
}

// ===========================================================================
// GEMM1 + swiglu: block 128m x 128 act-cols (256 B rows: 128 a + 128 b)
// ===========================================================================
__global__ __launch_bounds__(256, 1)
void gemm1_kernel() {
    const int e = blockIdx.z, mtile = blockIdx.y, ntile = blockIdx.x;
    const int tid = threadIdx.x, warp = tid >> 5, lane = tid & 31;
    const int wm = warp >> 2, wn = warp & 3;
    extern __shared__ char smem[];
    const uint32_t sb = s2u(smem);
    const int n0 = ntile * 128;

    // producers: thread -> rows (tid>>3)+32i, k-chunk (tid&7)
    const int r00 = tid >> 3, kc = tid & 7;
    const uint32_t aOff0 = (uint32_t)(r00 * RSB + kc * 16);
    const __half* aBase = g_Xh + ((size_t)(e * TOK_E + mtile * 128 + r00)) * HID + kc * 8;
    const __half* w1e   = g_W1t + (size_t)e * FFN2 * HID;
    const __half* bBaseA = w1e + (size_t)(n0 + r00) * HID + kc * 8;
    const __half* bBaseB = w1e + (size_t)(FFN + n0 + r00) * HID + kc * 8;

    float acc[2][4][4][4] = {};

    const uint32_t offM = (uint32_t)((lane & 15) * RSB + (lane >> 4) * 16);
    const uint32_t offN = (uint32_t)(((((lane >> 4) << 3) | (lane & 7))) * RSB + ((lane & 8) << 1));

    auto issue = [&](int kt) {
        if (kt < 32) {
            const uint32_t sa = sb + (uint32_t)(kt % 3) * STG;
            #pragma unroll
            for (int i = 0; i < 4; i++)
                cpa16(sa + aOff0 + i * (32 * RSB), aBase + (size_t)i * 32 * HID + kt * 64);
            const uint32_t sB = sa + A_STG;
            #pragma unroll
            for (int i = 0; i < 4; i++)
                cpa16(sB + aOff0 + i * (32 * RSB), bBaseA + (size_t)i * 32 * HID + kt * 64);
            #pragma unroll
            for (int i = 0; i < 4; i++)
                cpa16(sB + aOff0 + (i + 4) * (32 * RSB), bBaseB + (size_t)i * 32 * HID + kt * 64);
        }
        cp_commit();
    };

    issue(0); issue(1);
    for (int kt = 0; kt < 32; kt++) {
        cp_wait1();
        __syncthreads();
        const uint32_t sa = sb + (uint32_t)(kt % 3) * STG;
        const uint32_t sB = sa + A_STG;
        #pragma unroll
        for (int ks = 0; ks < 4; ks++) {
            const uint32_t kOff = ks * 32;
            uint32_t a[4][4];
            #pragma unroll
            for (int mt = 0; mt < 4; mt++)
                ldsm4(a[mt][0], a[mt][1], a[mt][2], a[mt][3],
                      sa + (uint32_t)((wm * 64 + mt * 16) * RSB) + kOff + offM);
            #pragma unroll
            for (int h = 0; h < 2; h++) {
                #pragma unroll
                for (int nq = 0; nq < 2; nq++) {
                    uint32_t b0, b1, b2, b3;
                    ldsm4(b0, b1, b2, b3,
                          sB + (uint32_t)((h * 128 + wn * 32 + nq * 16) * RSB) + kOff + offN);
                    #pragma unroll
                    for (int mt = 0; mt < 4; mt++) {
                        mma16(acc[h][mt][nq * 2 + 0], a[mt], b0, b1);
                        mma16(acc[h][mt][nq * 2 + 1], a[mt], b2, b3);
                    }
                }
            }
        }
        __syncthreads();
        issue(kt + 2);
    }

    // epilogue: swiglu -> fp16 act
    const int lg = lane >> 2, lt = lane & 3;
    __half* actBase = g_act + ((size_t)(e * TOK_E + mtile * 128)) * FFN + n0;
    #pragma unroll
    for (int mt = 0; mt < 4; mt++) {
        #pragma unroll
        for (int nt = 0; nt < 4; nt++) {
            const int r = wm * 64 + mt * 16 + lg;
            const int c = wn * 32 + nt * 8 + 2 * lt;
            const float* a = acc[0][mt][nt];
            const float* b = acc[1][mt][nt];
            __half2 v0 = __floats2half2_rn(silu(a[0]) * b[0], silu(a[1]) * b[1]);
            __half2 v1 = __floats2half2_rn(silu(a[2]) * b[2], silu(a[3]) * b[3]);
            *reinterpret_cast<__half2*>(actBase + (size_t)r * FFN + c)       = v0;
            *reinterpret_cast<__half2*>(actBase + (size_t)(r + 8) * FFN + c) = v1;
        }
    }
}

// ===========================================================================
// GEMM2: block 128m x 256n
// ===========================================================================
__global__ __launch_bounds__(256, 1)
void gemm2_kernel(float* __restrict__ out) {
    const int e = blockIdx.z, mtile = blockIdx.y, ntile = blockIdx.x;
    const int tid = threadIdx.x, warp = tid >> 5, lane = tid & 31;
    const int wm = warp >> 2, wn = warp & 3;
    extern __shared__ char smem[];
    const uint32_t sb = s2u(smem);
    const int n0 = ntile * 256;

    const int r00 = tid >> 3, kc = tid & 7;
    const uint32_t aOff0 = (uint32_t)(r00 * RSB + kc * 16);
    const __half* aBase = g_act + ((size_t)(e * TOK_E + mtile * 128 + r00)) * FFN + kc * 8;
    const __half* bBase = g_W2t + (size_t)e * HID * FFN + (size_t)(n0 + r00) * FFN + kc * 8;

    float acc[4][8][4] = {};

    const uint32_t offM = (uint32_t)((lane & 15) * RSB + (lane >> 4) * 16);
    const uint32_t offN = (uint32_t)(((((lane >> 4) << 3) | (lane & 7))) * RSB + ((lane & 8) << 1));

    auto issue = [&](int kt) {
        if (kt < 22) {
            const uint32_t sa = sb + (uint32_t)(kt % 3) * STG;
            #pragma unroll
            for (int i = 0; i < 4; i++)
                cpa16(sa + aOff0 + i * (32 * RSB), aBase + (size_t)i * 32 * FFN + kt * 64);
            const uint32_t sB = sa + A_STG;
            #pragma unroll
            for (int i = 0; i < 8; i++)
                cpa16(sB + aOff0 + i * (32 * RSB), bBase + (size_t)i * 32 * FFN + kt * 64);
        }
        cp_commit();
    };

    issue(0); issue(1);
    for (int kt = 0; kt < 22; kt++) {
        cp_wait1();
        __syncthreads();
        const uint32_t sa = sb + (uint32_t)(kt % 3) * STG;
        const uint32_t sB = sa + A_STG;
        #pragma unroll
        for (int ks = 0; ks < 4; ks++) {
            const uint32_t kOff = ks * 32;
            uint32_t a[4][4];
            #pragma unroll
            for (int mt = 0; mt < 4; mt++)
                ldsm4(a[mt][0], a[mt][1], a[mt][2], a[mt][3],
                      sa + (uint32_t)((wm * 64 + mt * 16) * RSB) + kOff + offM);
            #pragma unroll
            for (int nq = 0; nq < 4; nq++) {
                uint32_t b0, b1, b2, b3;
                ldsm4(b0, b1, b2, b3,
                      sB + (uint32_t)((wn * 64 + nq * 16) * RSB) + kOff + offN);
                #pragma unroll
                for (int mt = 0; mt < 4; mt++) {
                    mma16(acc[mt][nq * 2 + 0], a[mt], b0, b1);
                    mma16(acc[mt][nq * 2 + 1], a[mt], b2, b3);
                }
            }
        }
        __syncthreads();
        issue(kt + 2);
    }

    const int lg = lane >> 2, lt = lane & 3;
    float* outBase = out + ((size_t)(e * TOK_E + mtile * 128)) * HID + n0;
    #pragma unroll
    for (int mt = 0; mt < 4; mt++) {
        #pragma unroll
        for (int nt = 0; nt < 8; nt++) {
            const int r = wm * 64 + mt * 16 + lg;
            const int c = wn * 64 + nt * 8 + 2 * lt;
            const float* d = acc[mt][nt];
            *reinterpret_cast<float2*>(outBase + (size_t)r * HID + c)       = make_float2(d[0], d[1]);
            *reinterpret_cast<float2*>(outBase + (size_t)(r + 8) * HID + c) = make_float2(d[2], d[3]);
        }
    }
}

// ===========================================================================
// Launch
// ===========================================================================
extern "C" void kernel_launch(void* const* d_in, const int* in_sizes, int n_in,
                              void* d_out, int out_size) {
    const float* X  = (const float*)d_in[0];
    const float* W1 = (const float*)d_in[2];
    const float* W2 = (const float*)d_in[3];
    float* out = (float*)d_out;

    __half* w1t; cudaGetSymbolAddress((void**)&w1t, g_W1t);
    __half* w2t; cudaGetSymbolAddress((void**)&w2t, g_W2t);

    cudaFuncSetAttribute(gemm1_kernel, cudaFuncAttributeMaxDynamicSharedMemorySize, SMEM_TOTAL);
    cudaFuncSetAttribute(gemm2_kernel, cudaFuncAttributeMaxDynamicSharedMemorySize, SMEM_TOTAL);

    // pre-pass
    cvt_x_kernel<<<(TOK_E * NEXPERTS * (size_t)HID) / 4 / 256, 256>>>(X);
    transpose_cvt_kernel<<<dim3(FFN2 / 32, HID / 32, NEXPERTS), 256>>>(W1, w1t, HID, FFN2);
    transpose_cvt_kernel<<<dim3(HID / 32, FFN / 32, NEXPERTS), 256>>>(W2, w2t, FFN, HID);

    // GEMMs
    gemm1_kernel<<<dim3(FFN / 128, TOK_E / 128, NEXPERTS), 256, SMEM_TOTAL>>>();
    gemm2_kernel<<<dim3(HID / 256, TOK_E / 128, NEXPERTS), 256, SMEM_TOTAL>>>(out);
}

// round 5
// speedup vs baseline: 2.3452x; 1.5755x over previous
#include <cuda_runtime.h>
#include <cuda_fp16.h>
#include <cstdint>

// ---------------------------------------------------------------------------
// Experts MoE, fp16 mma.sync m16n8k16, fp32 accum (compute_103-safe).
// Round 5: 512 threads (16 warps, 32x64 warp tile), 1 sync/iter, 3-stage cp.async.
// Pre-pass: X -> fp16; W1,W2 -> transposed [n][k] fp16.
// ---------------------------------------------------------------------------

#define NEXPERTS 8
#define TOK_E    2048
#define HID      2048
#define FFN      1408
#define FFN2     2816

#define RSB   144               // smem row stride bytes (64 data halves + pad)
#define A_STG (128 * RSB)       // 18432
#define B_STG (256 * RSB)       // 36864
#define STG   (A_STG + B_STG)   // 55296
#define SMEM_TOTAL (3 * STG)    // 165888

__device__ __half g_Xh [(size_t)TOK_E * NEXPERTS * HID];
__device__ __half g_W1t[(size_t)NEXPERTS * FFN2 * HID];    // [e][n][k]
__device__ __half g_W2t[(size_t)NEXPERTS * HID * FFN];     // [e][n][k]
__device__ __half g_act[(size_t)NEXPERTS * TOK_E * FFN];

__device__ __forceinline__ uint32_t s2u(const void* p) {
    uint32_t a;
    asm("{ .reg .u64 t; cvta.to.shared.u64 t, %1; cvt.u32.u64 %0, t; }" : "=r"(a) : "l"(p));
    return a;
}
__device__ __forceinline__ void cpa16(uint32_t s, const void* g) {
    asm volatile("cp.async.cg.shared.global [%0], [%1], 16;" :: "r"(s), "l"(g));
}
__device__ __forceinline__ void cp_commit() {
    asm volatile("cp.async.commit_group;" ::: "memory");
}
__device__ __forceinline__ void cp_wait1() {
    asm volatile("cp.async.wait_group 1;" ::: "memory");
}
__device__ __forceinline__ void ldsm4(uint32_t& r0, uint32_t& r1, uint32_t& r2, uint32_t& r3,
                                      uint32_t addr) {
    asm volatile("ldmatrix.sync.aligned.m8n8.x4.shared.b16 {%0,%1,%2,%3}, [%4];"
                 : "=r"(r0), "=r"(r1), "=r"(r2), "=r"(r3) : "r"(addr));
}
__device__ __forceinline__ void mma16(float d[4], const uint32_t a[4], uint32_t b0, uint32_t b1) {
    asm volatile(
        "mma.sync.aligned.m16n8k16.row.col.f32.f16.f16.f32 "
        "{%0,%1,%2,%3}, {%4,%5,%6,%7}, {%8,%9}, {%0,%1,%2,%3};\n"
        : "+f"(d[0]), "+f"(d[1]), "+f"(d[2]), "+f"(d[3])
        : "r"(a[0]), "r"(a[1]), "r"(a[2]), "r"(a[3]), "r"(b0), "r"(b1));
}
__device__ __forceinline__ float silu(float x) { return x / (1.0f + __expf(-x)); }

// ===========================================================================
// Pre-pass kernels
// ===========================================================================
__global__ __launch_bounds__(256)
void cvt_x_kernel(const float* __restrict__ X) {
    size_t i = (size_t)blockIdx.x * blockDim.x + threadIdx.x;
    float4 v = reinterpret_cast<const float4*>(X)[i];
    __half2* o = reinterpret_cast<__half2*>(g_Xh) + 2 * i;
    o[0] = __floats2half2_rn(v.x, v.y);
    o[1] = __floats2half2_rn(v.z, v.w);
}

__global__ __launch_bounds__(256)
void transpose_cvt_kernel(const float* __restrict__ in, __half* __restrict__ out,
                          int R, int C) {
    __shared__ float tile[32][33];
    const size_t eo = (size_t)blockIdx.z * R * C;
    const int r0 = blockIdx.y * 32, c0 = blockIdx.x * 32;
    const int tx = threadIdx.x & 31, ty = threadIdx.x >> 5;
    #pragma unroll
    for (int j = 0; j < 32; j += 8)
        tile[ty + j][tx] = in[eo + (size_t)(r0 + ty + j) * C + c0 + tx];
    __syncthreads();
    #pragma unroll
    for (int j = 0; j < 32; j += 8)
        out[eo + (size_t)(c0 + ty + j) * R + r0 + tx] = __float2half_rn(tile[tx][ty + j]);
}

// ===========================================================================
// GEMM1 + swiglu: block 128m x 128 act-cols. B = 256 rows interleaved at
// 32-col granularity: [a(0:32), b(0:32), a(32:64), b(32:64), ...] so each
// warp's 64 n-rows hold 32 matching a/b column pairs (intra-warp swiglu).
// 512 threads = 16 warps, 4m x 4n, warp tile 32x64, BK=64, 3 stages.
// ===========================================================================
__global__ __launch_bounds__(512, 1)
void gemm1_kernel() {
    const int e = blockIdx.z, mtile = blockIdx.y, ntile = blockIdx.x;
    const int tid = threadIdx.x, warp = tid >> 5, lane = tid & 31;
    const int wm = warp >> 2, wn = warp & 3;
    extern __shared__ char smem[];
    const uint32_t sb = s2u(smem);
    const int n0 = ntile * 128;

    // producers: thread -> A rows pr, pr+64; B rows pr+64i; chunk kc (16B)
    const int pr = tid >> 3, kc = tid & 7;
    const uint32_t aOff = (uint32_t)(pr * RSB + kc * 16);
    const __half* aBase = g_Xh + ((size_t)(e * TOK_E + mtile * 128 + pr)) * HID + kc * 8;
    const __half* w1e = g_W1t + (size_t)e * FFN2 * HID;
    const __half* bPtr[4];
    #pragma unroll
    for (int i = 0; i < 4; i++) {
        int r = pr + 64 * i;
        int g = r >> 5, w = r & 31;
        int col = n0 + (g >> 1) * 32 + w + (g & 1) * FFN;
        bPtr[i] = w1e + (size_t)col * HID + kc * 8;
    }

    float acc[2][8][4] = {};
    const uint32_t offM = (uint32_t)((lane & 15) * RSB + (lane >> 4) * 16);
    const uint32_t offN = (uint32_t)(((((lane >> 4) << 3) | (lane & 7))) * RSB + ((lane & 8) << 1));

    auto issue = [&](int kt) {
        if (kt < 32) {
            const uint32_t s = sb + (uint32_t)(kt % 3) * STG;
            cpa16(s + aOff,           aBase + (size_t)kt * 64);
            cpa16(s + aOff + 64 * RSB, aBase + (size_t)64 * HID + (size_t)kt * 64);
            const uint32_t sB = s + A_STG;
            #pragma unroll
            for (int i = 0; i < 4; i++)
                cpa16(sB + aOff + i * (64 * RSB), bPtr[i] + (size_t)kt * 64);
        }
        cp_commit();
    };

    issue(0); issue(1);
    for (int kt = 0; kt < 32; kt++) {
        cp_wait1();
        __syncthreads();
        issue(kt + 2);
        const uint32_t sa = sb + (uint32_t)(kt % 3) * STG;
        const uint32_t sB = sa + A_STG;
        #pragma unroll
        for (int ks = 0; ks < 4; ks++) {
            const uint32_t kOff = ks * 32;
            uint32_t a[2][4];
            #pragma unroll
            for (int mt = 0; mt < 2; mt++)
                ldsm4(a[mt][0], a[mt][1], a[mt][2], a[mt][3],
                      sa + (uint32_t)((wm * 32 + mt * 16) * RSB) + kOff + offM);
            #pragma unroll
            for (int nq = 0; nq < 4; nq++) {
                uint32_t b0, b1, b2, b3;
                ldsm4(b0, b1, b2, b3,
                      sB + (uint32_t)((wn * 64 + nq * 16) * RSB) + kOff + offN);
                #pragma unroll
                for (int mt = 0; mt < 2; mt++) {
                    mma16(acc[mt][nq * 2 + 0], a[mt], b0, b1);
                    mma16(acc[mt][nq * 2 + 1], a[mt], b2, b3);
                }
            }
        }
    }

    // epilogue: tiles 0..3 = a-cols, 4..7 = matching b-cols
    const int lg = lane >> 2, lt = lane & 3;
    __half* actBase = g_act + ((size_t)(e * TOK_E + mtile * 128)) * FFN + n0 + wn * 32;
    #pragma unroll
    for (int mt = 0; mt < 2; mt++) {
        #pragma unroll
        for (int j = 0; j < 4; j++) {
            const int r = wm * 32 + mt * 16 + lg;
            const int c = 8 * j + 2 * lt;
            const float* pa = acc[mt][j];
            const float* pb = acc[mt][4 + j];
            __half2 v0 = __floats2half2_rn(silu(pa[0]) * pb[0], silu(pa[1]) * pb[1]);
            __half2 v1 = __floats2half2_rn(silu(pa[2]) * pb[2], silu(pa[3]) * pb[3]);
            *reinterpret_cast<__half2*>(actBase + (size_t)r * FFN + c)       = v0;
            *reinterpret_cast<__half2*>(actBase + (size_t)(r + 8) * FFN + c) = v1;
        }
    }
}

// ===========================================================================
// GEMM2: block 128m x 256n, 512 threads, warp tile 32x64, BK=64, 3 stages.
// ===========================================================================
__global__ __launch_bounds__(512, 1)
void gemm2_kernel(float* __restrict__ out) {
    const int e = blockIdx.z, mtile = blockIdx.y, ntile = blockIdx.x;
    const int tid = threadIdx.x, warp = tid >> 5, lane = tid & 31;
    const int wm = warp >> 2, wn = warp & 3;
    extern __shared__ char smem[];
    const uint32_t sb = s2u(smem);
    const int n0 = ntile * 256;

    const int pr = tid >> 3, kc = tid & 7;
    const uint32_t aOff = (uint32_t)(pr * RSB + kc * 16);
    const __half* aBase = g_act + ((size_t)(e * TOK_E + mtile * 128 + pr)) * FFN + kc * 8;
    const __half* bBase = g_W2t + (size_t)e * HID * FFN + (size_t)(n0 + pr) * FFN + kc * 8;

    float acc[2][8][4] = {};
    const uint32_t offM = (uint32_t)((lane & 15) * RSB + (lane >> 4) * 16);
    const uint32_t offN = (uint32_t)(((((lane >> 4) << 3) | (lane & 7))) * RSB + ((lane & 8) << 1));

    auto issue = [&](int kt) {
        if (kt < 22) {
            const uint32_t s = sb + (uint32_t)(kt % 3) * STG;
            cpa16(s + aOff,            aBase + (size_t)kt * 64);
            cpa16(s + aOff + 64 * RSB, aBase + (size_t)64 * FFN + (size_t)kt * 64);
            const uint32_t sB = s + A_STG;
            #pragma unroll
            for (int i = 0; i < 4; i++)
                cpa16(sB + aOff + i * (64 * RSB), bBase + (size_t)(64 * i) * FFN + (size_t)kt * 64);
        }
        cp_commit();
    };

    issue(0); issue(1);
    for (int kt = 0; kt < 22; kt++) {
        cp_wait1();
        __syncthreads();
        issue(kt + 2);
        const uint32_t sa = sb + (uint32_t)(kt % 3) * STG;
        const uint32_t sB = sa + A_STG;
        #pragma unroll
        for (int ks = 0; ks < 4; ks++) {
            const uint32_t kOff = ks * 32;
            uint32_t a[2][4];
            #pragma unroll
            for (int mt = 0; mt < 2; mt++)
                ldsm4(a[mt][0], a[mt][1], a[mt][2], a[mt][3],
                      sa + (uint32_t)((wm * 32 + mt * 16) * RSB) + kOff + offM);
            #pragma unroll
            for (int nq = 0; nq < 4; nq++) {
                uint32_t b0, b1, b2, b3;
                ldsm4(b0, b1, b2, b3,
                      sB + (uint32_t)((wn * 64 + nq * 16) * RSB) + kOff + offN);
                #pragma unroll
                for (int mt = 0; mt < 2; mt++) {
                    mma16(acc[mt][nq * 2 + 0], a[mt], b0, b1);
                    mma16(acc[mt][nq * 2 + 1], a[mt], b2, b3);
                }
            }
        }
    }

    const int lg = lane >> 2, lt = lane & 3;
    float* outBase = out + ((size_t)(e * TOK_E + mtile * 128)) * HID + n0 + wn * 64;
    #pragma unroll
    for (int mt = 0; mt < 2; mt++) {
        #pragma unroll
        for (int j = 0; j < 8; j++) {
            const int r = wm * 32 + mt * 16 + lg;
            const int c = 8 * j + 2 * lt;
            const float* d = acc[mt][j];
            *reinterpret_cast<float2*>(outBase + (size_t)r * HID + c)       = make_float2(d[0], d[1]);
            *reinterpret_cast<float2*>(outBase + (size_t)(r + 8) * HID + c) = make_float2(d[2], d[3]);
        }
    }
}

// ===========================================================================
// Launch
// ===========================================================================
extern "C" void kernel_launch(void* const* d_in, const int* in_sizes, int n_in,
                              void* d_out, int out_size) {
    const float* X  = (const float*)d_in[0];
    const float* W1 = (const float*)d_in[2];
    const float* W2 = (const float*)d_in[3];
    float* out = (float*)d_out;

    __half* w1t; cudaGetSymbolAddress((void**)&w1t, g_W1t);
    __half* w2t; cudaGetSymbolAddress((void**)&w2t, g_W2t);

    cudaFuncSetAttribute(gemm1_kernel, cudaFuncAttributeMaxDynamicSharedMemorySize, SMEM_TOTAL);
    cudaFuncSetAttribute(gemm2_kernel, cudaFuncAttributeMaxDynamicSharedMemorySize, SMEM_TOTAL);

    cvt_x_kernel<<<(TOK_E * NEXPERTS * (size_t)HID) / 4 / 256, 256>>>(X);
    transpose_cvt_kernel<<<dim3(FFN2 / 32, HID / 32, NEXPERTS), 256>>>(W1, w1t, HID, FFN2);
    transpose_cvt_kernel<<<dim3(HID / 32, FFN / 32, NEXPERTS), 256>>>(W2, w2t, FFN, HID);

    gemm1_kernel<<<dim3(FFN / 128, TOK_E / 128, NEXPERTS), 512, SMEM_TOTAL>>>();
    gemm2_kernel<<<dim3(HID / 256, TOK_E / 128, NEXPERTS), 512, SMEM_TOTAL>>>(out);
}

// round 6
// speedup vs baseline: 2.9751x; 1.2686x over previous
#include <cuda_runtime.h>
#include <cuda_fp16.h>
#include <cstdint>

// ---------------------------------------------------------------------------
// Experts MoE, fp16 mma.sync m16n8k16, fp32 accum (compute_103-safe).
// Round 6: 2 CTAs/SM (256 thr, 128x128 block, 32x64 warp tile), XOR-swizzled
// smem (no padding), 3-stage cp.async. Independent CTAs overlap barrier stalls.
// ---------------------------------------------------------------------------

#define NEXPERTS 8
#define TOK_E    2048
#define HID      2048
#define FFN      1408
#define FFN2     2816

// swizzled tile: 128 rows x 128B (64 halves), phys(row,chunk)=row*128+((chunk^(row&7))<<4)
#define TILE_B (128 * 128)              // 16384
#define STG    (2 * TILE_B)             // 32768 (A + B)
#define SMEM_TOTAL (3 * STG)            // 98304

__device__ __half g_Xh [(size_t)TOK_E * NEXPERTS * HID];
__device__ __half g_W1t[(size_t)NEXPERTS * FFN2 * HID];    // [e][n][k]
__device__ __half g_W2t[(size_t)NEXPERTS * HID * FFN];     // [e][n][k]
__device__ __half g_act[(size_t)NEXPERTS * TOK_E * FFN];

__device__ __forceinline__ uint32_t s2u(const void* p) {
    uint32_t a;
    asm("{ .reg .u64 t; cvta.to.shared.u64 t, %1; cvt.u32.u64 %0, t; }" : "=r"(a) : "l"(p));
    return a;
}
__device__ __forceinline__ void cpa16(uint32_t s, const void* g) {
    asm volatile("cp.async.cg.shared.global [%0], [%1], 16;" :: "r"(s), "l"(g));
}
__device__ __forceinline__ void cp_commit() {
    asm volatile("cp.async.commit_group;" ::: "memory");
}
__device__ __forceinline__ void cp_wait1() {
    asm volatile("cp.async.wait_group 1;" ::: "memory");
}
__device__ __forceinline__ void ldsm4(uint32_t& r0, uint32_t& r1, uint32_t& r2, uint32_t& r3,
                                      uint32_t addr) {
    asm volatile("ldmatrix.sync.aligned.m8n8.x4.shared.b16 {%0,%1,%2,%3}, [%4];"
                 : "=r"(r0), "=r"(r1), "=r"(r2), "=r"(r3) : "r"(addr));
}
__device__ __forceinline__ void mma16(float d[4], const uint32_t a[4], uint32_t b0, uint32_t b1) {
    asm volatile(
        "mma.sync.aligned.m16n8k16.row.col.f32.f16.f16.f32 "
        "{%0,%1,%2,%3}, {%4,%5,%6,%7}, {%8,%9}, {%0,%1,%2,%3};\n"
        : "+f"(d[0]), "+f"(d[1]), "+f"(d[2]), "+f"(d[3])
        : "r"(a[0]), "r"(a[1]), "r"(a[2]), "r"(a[3]), "r"(b0), "r"(b1));
}
__device__ __forceinline__ float silu(float x) { return x / (1.0f + __expf(-x)); }

// ===========================================================================
// Pre-pass kernels
// ===========================================================================
__global__ __launch_bounds__(256)
void cvt_x_kernel(const float* __restrict__ X) {
    size_t i = (size_t)blockIdx.x * blockDim.x + threadIdx.x;
    float4 v = reinterpret_cast<const float4*>(X)[i];
    __half2* o = reinterpret_cast<__half2*>(g_Xh) + 2 * i;
    o[0] = __floats2half2_rn(v.x, v.y);
    o[1] = __floats2half2_rn(v.z, v.w);
}

__global__ __launch_bounds__(256)
void transpose_cvt_kernel(const float* __restrict__ in, __half* __restrict__ out,
                          int R, int C) {
    __shared__ float tile[32][33];
    const size_t eo = (size_t)blockIdx.z * R * C;
    const int r0 = blockIdx.y * 32, c0 = blockIdx.x * 32;
    const int tx = threadIdx.x & 31, ty = threadIdx.x >> 5;
    #pragma unroll
    for (int j = 0; j < 32; j += 8)
        tile[ty + j][tx] = in[eo + (size_t)(r0 + ty + j) * C + c0 + tx];
    __syncthreads();
    #pragma unroll
    for (int j = 0; j < 32; j += 8)
        out[eo + (size_t)(c0 + ty + j) * R + r0 + tx] = __float2half_rn(tile[tx][ty + j]);
}

// ===========================================================================
// GEMM mainloop shared machinery (both kernels have identical structure).
// 8 warps = 4m x 2n, warp tile 32x64. A,B tiles 128 rows x 64 halves, swizzled.
// ===========================================================================

// GEMM1 + swiglu: block 128m x 64 act-cols (B rows: [a0-31,b0-31,a32-63,b32-63])
__global__ __launch_bounds__(256, 2)
void gemm1_kernel() {
    const int e = blockIdx.z, mtile = blockIdx.y, ntile = blockIdx.x;
    const int tid = threadIdx.x, warp = tid >> 5, lane = tid & 31;
    const int wm = warp >> 1, wn = warp & 1;
    extern __shared__ char smem[];
    const uint32_t sb = s2u(smem);
    const int n0 = ntile * 64;

    // producers: thread -> rows pr+32i, chunk kc; swizzled dst offset
    const int pr = tid >> 3, kc = tid & 7;
    const uint32_t swc = (uint32_t)((kc ^ (pr & 7)) << 4);
    uint32_t dOff[4];
    #pragma unroll
    for (int i = 0; i < 4; i++) dOff[i] = (uint32_t)((pr + 32 * i) * 128) + swc;

    const __half* aSrc[4];
    const __half* bSrc[4];
    {
        const __half* xe  = g_Xh + ((size_t)(e * TOK_E + mtile * 128)) * HID + kc * 8;
        const __half* w1e = g_W1t + (size_t)e * FFN2 * HID + kc * 8;
        #pragma unroll
        for (int i = 0; i < 4; i++) {
            aSrc[i] = xe + (size_t)(pr + 32 * i) * HID;
            const int col = n0 + (i >> 1) * 32 + pr + (i & 1) * FFN;
            bSrc[i] = w1e + (size_t)col * HID;
        }
    }

    // consumer fragment address pieces
    const int hiA = lane >> 4;
    uint32_t aRow[2], aS[2];
    #pragma unroll
    for (int mt = 0; mt < 2; mt++) {
        const int r = wm * 32 + mt * 16 + (lane & 15);
        aRow[mt] = (uint32_t)(r * 128); aS[mt] = (uint32_t)(r & 7);
    }
    const int hiB = (lane >> 3) & 1;
    uint32_t bRow[4], bS[4];
    #pragma unroll
    for (int nq = 0; nq < 4; nq++) {
        const int r = wn * 64 + nq * 16 + ((lane >> 4) << 3) + (lane & 7);
        bRow[nq] = (uint32_t)(r * 128); bS[nq] = (uint32_t)(r & 7);
    }

    float acc[2][8][4] = {};

    auto issue = [&](int kt) {
        if (kt < 32) {
            const uint32_t s  = sb + (uint32_t)(kt % 3) * STG;
            const uint32_t sB = s + TILE_B;
            #pragma unroll
            for (int i = 0; i < 4; i++) cpa16(s  + dOff[i], aSrc[i] + (size_t)kt * 64);
            #pragma unroll
            for (int i = 0; i < 4; i++) cpa16(sB + dOff[i], bSrc[i] + (size_t)kt * 64);
        }
        cp_commit();
    };

    issue(0); issue(1);
    for (int kt = 0; kt < 32; kt++) {
        cp_wait1();
        __syncthreads();
        issue(kt + 2);
        const uint32_t sa = sb + (uint32_t)(kt % 3) * STG;
        const uint32_t sB = sa + TILE_B;
        #pragma unroll
        for (int ks = 0; ks < 4; ks++) {
            uint32_t a[2][4];
            #pragma unroll
            for (int mt = 0; mt < 2; mt++)
                ldsm4(a[mt][0], a[mt][1], a[mt][2], a[mt][3],
                      sa + aRow[mt] + ((((uint32_t)(2 * ks) + hiA) ^ aS[mt]) << 4));
            #pragma unroll
            for (int nq = 0; nq < 4; nq++) {
                uint32_t b0, b1, b2, b3;
                ldsm4(b0, b1, b2, b3,
                      sB + bRow[nq] + ((((uint32_t)(2 * ks) + hiB) ^ bS[nq]) << 4));
                #pragma unroll
                for (int mt = 0; mt < 2; mt++) {
                    mma16(acc[mt][nq * 2 + 0], a[mt], b0, b1);
                    mma16(acc[mt][nq * 2 + 1], a[mt], b2, b3);
                }
            }
        }
    }

    // epilogue: j 0..3 = a-cols, j+4 = matching b-cols (interleaved B rows)
    const int lg = lane >> 2, lt = lane & 3;
    __half* actBase = g_act + ((size_t)(e * TOK_E + mtile * 128)) * FFN + n0 + wn * 32;
    #pragma unroll
    for (int mt = 0; mt < 2; mt++) {
        #pragma unroll
        for (int j = 0; j < 4; j++) {
            const int r = wm * 32 + mt * 16 + lg;
            const int c = 8 * j + 2 * lt;
            const float* pa = acc[mt][j];
            const float* pb = acc[mt][4 + j];
            __half2 v0 = __floats2half2_rn(silu(pa[0]) * pb[0], silu(pa[1]) * pb[1]);
            __half2 v1 = __floats2half2_rn(silu(pa[2]) * pb[2], silu(pa[3]) * pb[3]);
            *reinterpret_cast<__half2*>(actBase + (size_t)r * FFN + c)       = v0;
            *reinterpret_cast<__half2*>(actBase + (size_t)(r + 8) * FFN + c) = v1;
        }
    }
}

// GEMM2: block 128m x 128n
__global__ __launch_bounds__(256, 2)
void gemm2_kernel(float* __restrict__ out) {
    const int e = blockIdx.z, mtile = blockIdx.y, ntile = blockIdx.x;
    const int tid = threadIdx.x, warp = tid >> 5, lane = tid & 31;
    const int wm = warp >> 1, wn = warp & 1;
    extern __shared__ char smem[];
    const uint32_t sb = s2u(smem);
    const int n0 = ntile * 128;

    const int pr = tid >> 3, kc = tid & 7;
    const uint32_t swc = (uint32_t)((kc ^ (pr & 7)) << 4);
    uint32_t dOff[4];
    #pragma unroll
    for (int i = 0; i < 4; i++) dOff[i] = (uint32_t)((pr + 32 * i) * 128) + swc;

    const __half* aSrc[4];
    const __half* bSrc[4];
    {
        const __half* ae  = g_act + ((size_t)(e * TOK_E + mtile * 128)) * FFN + kc * 8;
        const __half* w2e = g_W2t + (size_t)e * HID * FFN + kc * 8;
        #pragma unroll
        for (int i = 0; i < 4; i++) {
            aSrc[i] = ae  + (size_t)(pr + 32 * i) * FFN;
            bSrc[i] = w2e + (size_t)(n0 + pr + 32 * i) * FFN;
        }
    }

    const int hiA = lane >> 4;
    uint32_t aRow[2], aS[2];
    #pragma unroll
    for (int mt = 0; mt < 2; mt++) {
        const int r = wm * 32 + mt * 16 + (lane & 15);
        aRow[mt] = (uint32_t)(r * 128); aS[mt] = (uint32_t)(r & 7);
    }
    const int hiB = (lane >> 3) & 1;
    uint32_t bRow[4], bS[4];
    #pragma unroll
    for (int nq = 0; nq < 4; nq++) {
        const int r = wn * 64 + nq * 16 + ((lane >> 4) << 3) + (lane & 7);
        bRow[nq] = (uint32_t)(r * 128); bS[nq] = (uint32_t)(r & 7);
    }

    float acc[2][8][4] = {};

    auto issue = [&](int kt) {
        if (kt < 22) {
            const uint32_t s  = sb + (uint32_t)(kt % 3) * STG;
            const uint32_t sB = s + TILE_B;
            #pragma unroll
            for (int i = 0; i < 4; i++) cpa16(s  + dOff[i], aSrc[i] + (size_t)kt * 64);
            #pragma unroll
            for (int i = 0; i < 4; i++) cpa16(sB + dOff[i], bSrc[i] + (size_t)kt * 64);
        }
        cp_commit();
    };

    issue(0); issue(1);
    for (int kt = 0; kt < 22; kt++) {
        cp_wait1();
        __syncthreads();
        issue(kt + 2);
        const uint32_t sa = sb + (uint32_t)(kt % 3) * STG;
        const uint32_t sB = sa + TILE_B;
        #pragma unroll
        for (int ks = 0; ks < 4; ks++) {
            uint32_t a[2][4];
            #pragma unroll
            for (int mt = 0; mt < 2; mt++)
                ldsm4(a[mt][0], a[mt][1], a[mt][2], a[mt][3],
                      sa + aRow[mt] + ((((uint32_t)(2 * ks) + hiA) ^ aS[mt]) << 4));
            #pragma unroll
            for (int nq = 0; nq < 4; nq++) {
                uint32_t b0, b1, b2, b3;
                ldsm4(b0, b1, b2, b3,
                      sB + bRow[nq] + ((((uint32_t)(2 * ks) + hiB) ^ bS[nq]) << 4));
                #pragma unroll
                for (int mt = 0; mt < 2; mt++) {
                    mma16(acc[mt][nq * 2 + 0], a[mt], b0, b1);
                    mma16(acc[mt][nq * 2 + 1], a[mt], b2, b3);
                }
            }
        }
    }

    const int lg = lane >> 2, lt = lane & 3;
    float* outBase = out + ((size_t)(e * TOK_E + mtile * 128)) * HID + n0 + wn * 64;
    #pragma unroll
    for (int mt = 0; mt < 2; mt++) {
        #pragma unroll
        for (int j = 0; j < 8; j++) {
            const int r = wm * 32 + mt * 16 + lg;
            const int c = 8 * j + 2 * lt;
            const float* d = acc[mt][j];
            *reinterpret_cast<float2*>(outBase + (size_t)r * HID + c)       = make_float2(d[0], d[1]);
            *reinterpret_cast<float2*>(outBase + (size_t)(r + 8) * HID + c) = make_float2(d[2], d[3]);
        }
    }
}

// ===========================================================================
// Launch
// ===========================================================================
extern "C" void kernel_launch(void* const* d_in, const int* in_sizes, int n_in,
                              void* d_out, int out_size) {
    const float* X  = (const float*)d_in[0];
    const float* W1 = (const float*)d_in[2];
    const float* W2 = (const float*)d_in[3];
    float* out = (float*)d_out;

    __half* w1t; cudaGetSymbolAddress((void**)&w1t, g_W1t);
    __half* w2t; cudaGetSymbolAddress((void**)&w2t, g_W2t);

    cudaFuncSetAttribute(gemm1_kernel, cudaFuncAttributeMaxDynamicSharedMemorySize, SMEM_TOTAL);
    cudaFuncSetAttribute(gemm2_kernel, cudaFuncAttributeMaxDynamicSharedMemorySize, SMEM_TOTAL);

    cvt_x_kernel<<<(TOK_E * NEXPERTS * (size_t)HID) / 4 / 256, 256>>>(X);
    transpose_cvt_kernel<<<dim3(FFN2 / 32, HID / 32, NEXPERTS), 256>>>(W1, w1t, HID, FFN2);
    transpose_cvt_kernel<<<dim3(HID / 32, FFN / 32, NEXPERTS), 256>>>(W2, w2t, FFN, HID);

    gemm1_kernel<<<dim3(FFN / 64,  TOK_E / 128, NEXPERTS), 256, SMEM_TOTAL>>>();
    gemm2_kernel<<<dim3(HID / 128, TOK_E / 128, NEXPERTS), 256, SMEM_TOTAL>>>(out);
}

// round 7
// speedup vs baseline: 2.9983x; 1.0078x over previous
#include <cuda_runtime.h>
#include <cuda_fp16.h>
#include <cstdint>

// ---------------------------------------------------------------------------
// Experts MoE, fp16 mma.sync m16n8k16, fp32 accum (compute_103-safe).
// Round 7: B stages stored [k][n] (native W layout) + ldmatrix.trans -> the
// weight prepass is a pure streaming convert (no transpose). W2 convert is
// folded into gemm1's grid so it hides behind the tensor-bound mainloop.
// 2 CTAs/SM, 128x128 block, 32x64 warp tile, XOR-swizzled smem, 3-stage cp.async.
// ---------------------------------------------------------------------------

#define NEXPERTS 8
#define TOK_E    2048
#define HID      2048
#define FFN      1408
#define FFN2     2816

// A tile: 128 m-rows x 128B (64 halves).  B tile: 64 k-rows x 256B (128 halves).
#define TILE_B 16384
#define STG    (2 * TILE_B)             // 32768
#define SMEM_TOTAL (3 * STG)            // 98304

#define W2_CVT_CTAS 64
#define W2_F4_PER_CTA 90112             // (8*1408*2048/4)/64
#define W2_F4_PER_THR 352               // /256

__device__ __half g_Xh [(size_t)TOK_E * NEXPERTS * HID];
__device__ __half g_W1h[(size_t)NEXPERTS * HID * FFN2];    // [e][k][n] fp16
__device__ __half g_W2h[(size_t)NEXPERTS * FFN * HID];     // [e][k][n] fp16
__device__ __half g_act[(size_t)NEXPERTS * TOK_E * FFN];

__device__ __forceinline__ uint32_t s2u(const void* p) {
    uint32_t a;
    asm("{ .reg .u64 t; cvta.to.shared.u64 t, %1; cvt.u32.u64 %0, t; }" : "=r"(a) : "l"(p));
    return a;
}
__device__ __forceinline__ void cpa16(uint32_t s, const void* g) {
    asm volatile("cp.async.cg.shared.global [%0], [%1], 16;" :: "r"(s), "l"(g));
}
__device__ __forceinline__ void cp_commit() {
    asm volatile("cp.async.commit_group;" ::: "memory");
}
__device__ __forceinline__ void cp_wait1() {
    asm volatile("cp.async.wait_group 1;" ::: "memory");
}
__device__ __forceinline__ void ldsm4(uint32_t& r0, uint32_t& r1, uint32_t& r2, uint32_t& r3,
                                      uint32_t addr) {
    asm volatile("ldmatrix.sync.aligned.m8n8.x4.shared.b16 {%0,%1,%2,%3}, [%4];"
                 : "=r"(r0), "=r"(r1), "=r"(r2), "=r"(r3) : "r"(addr));
}
__device__ __forceinline__ void ldsm4t(uint32_t& r0, uint32_t& r1, uint32_t& r2, uint32_t& r3,
                                       uint32_t addr) {
    asm volatile("ldmatrix.sync.aligned.m8n8.x4.trans.shared.b16 {%0,%1,%2,%3}, [%4];"
                 : "=r"(r0), "=r"(r1), "=r"(r2), "=r"(r3) : "r"(addr));
}
__device__ __forceinline__ void mma16(float d[4], const uint32_t a[4], uint32_t b0, uint32_t b1) {
    asm volatile(
        "mma.sync.aligned.m16n8k16.row.col.f32.f16.f16.f32 "
        "{%0,%1,%2,%3}, {%4,%5,%6,%7}, {%8,%9}, {%0,%1,%2,%3};\n"
        : "+f"(d[0]), "+f"(d[1]), "+f"(d[2]), "+f"(d[3])
        : "r"(a[0]), "r"(a[1]), "r"(a[2]), "r"(a[3]), "r"(b0), "r"(b1));
}
__device__ __forceinline__ float silu(float x) { return x / (1.0f + __expf(-x)); }

__device__ __forceinline__ uint2 cvt4h(float4 v) {
    __half2 h0 = __floats2half2_rn(v.x, v.y);
    __half2 h1 = __floats2half2_rn(v.z, v.w);
    uint2 u;
    u.x = *reinterpret_cast<uint32_t*>(&h0);
    u.y = *reinterpret_cast<uint32_t*>(&h1);
    return u;
}

// ===========================================================================
// Generic streaming f32 -> fp16 convert (grid-stride, float4 -> half2x2)
// ===========================================================================
__global__ __launch_bounds__(256)
void cvt_kernel(const float* __restrict__ src, __half* __restrict__ dst, size_t n4) {
    const float4* s4 = reinterpret_cast<const float4*>(src);
    uint2* d4 = reinterpret_cast<uint2*>(dst);
    for (size_t i = (size_t)blockIdx.x * blockDim.x + threadIdx.x; i < n4;
         i += (size_t)gridDim.x * blockDim.x)
        d4[i] = cvt4h(s4[i]);
}

// ===========================================================================
// GEMM1 + swiglu. ntile 0..21 = GEMM (128m x 64 act-cols); ntile 22 = W2 cvt.
// B stage n-cols: [a(0:32) | b(0:32) | a(32:64) | b(32:64)] (k-major rows).
// ===========================================================================
__global__ __launch_bounds__(256, 2)
void gemm1_kernel(const float* __restrict__ W2src) {
    // ---- embedded W2 convert CTAs (hidden behind the GEMM CTAs) ----
    if (blockIdx.x == 22) {
        if (blockIdx.y >= 8) return;
        const size_t cid = (size_t)blockIdx.z * 8 + blockIdx.y;   // 0..63
        const float4* s4 = reinterpret_cast<const float4*>(W2src) + cid * W2_F4_PER_CTA;
        uint2* d4 = reinterpret_cast<uint2*>(g_W2h) + cid * W2_F4_PER_CTA;
        #pragma unroll 4
        for (int i = threadIdx.x; i < W2_F4_PER_CTA; i += 256)
            d4[i] = cvt4h(s4[i]);
        return;
    }

    const int e = blockIdx.z, mtile = blockIdx.y, ntile = blockIdx.x;
    const int tid = threadIdx.x, warp = tid >> 5, lane = tid & 31;
    const int wm = warp >> 1, wn = warp & 1;
    extern __shared__ char smem[];
    const uint32_t sb = s2u(smem);
    const int n0 = ntile * 64;

    // ---- A producer: [m][k] tile, rows pr+32i, chunk kc ----
    const int pr = tid >> 3, kc = tid & 7;
    const uint32_t swcA = (uint32_t)((kc ^ (pr & 7)) << 4);
    uint32_t dOffA[4];
    const __half* aSrc[4];
    {
        const __half* xe = g_Xh + ((size_t)(e * TOK_E + mtile * 128)) * HID + kc * 8;
        #pragma unroll
        for (int i = 0; i < 4; i++) {
            dOffA[i] = (uint32_t)((pr + 32 * i) * 128) + swcA;
            aSrc[i]  = xe + (size_t)(pr + 32 * i) * HID;
        }
    }

    // ---- B producer: [k][n] tile, 64 rows x 16 chunks; thread: rows {rB,rB+32},
    //      chunks {cB, cB+8}; gmem col depends on chunk (interleaved a/b groups) ----
    const int rB = tid >> 3, cB = tid & 7;
    uint32_t dOffB[4];
    const __half* bSrc[4];
    {
        const __half* w1e = g_W1h + (size_t)e * HID * FFN2;
        #pragma unroll
        for (int j = 0; j < 4; j++) {
            const int row = rB + (j >> 1) * 32;
            const int ch  = cB + (j & 1) * 8;
            const int g   = ch >> 2;
            const int col = n0 + (g >> 1) * 32 + (ch & 3) * 8 + ((g & 1) ? FFN : 0);
            dOffB[j] = (uint32_t)(row * 256 + ((ch ^ (rB & 7)) << 4));
            bSrc[j]  = w1e + (size_t)row * FFN2 + col;
        }
    }

    // ---- consumer fragment addressing ----
    const uint32_t hiA = lane >> 4;
    uint32_t aRow[2], aS[2];
    #pragma unroll
    for (int mt = 0; mt < 2; mt++) {
        const int r = wm * 32 + mt * 16 + (lane & 15);
        aRow[mt] = (uint32_t)(r * 128); aS[mt] = (uint32_t)(r & 7);
    }
    const uint32_t rowB = (uint32_t)((((lane >> 3) & 1) * 8 + (lane & 7)) * 256);
    uint32_t swB[4];
    #pragma unroll
    for (int nq = 0; nq < 4; nq++)
        swB[nq] = (uint32_t)((((wn * 8 + nq * 2 + (lane >> 4)) ^ (lane & 7))) << 4);

    float acc[2][8][4] = {};

    auto issue = [&](int kt) {
        if (kt < 32) {
            const uint32_t s  = sb + (uint32_t)(kt % 3) * STG;
            const uint32_t sB = s + TILE_B;
            #pragma unroll
            for (int i = 0; i < 4; i++) cpa16(s  + dOffA[i], aSrc[i] + (size_t)kt * 64);
            #pragma unroll
            for (int j = 0; j < 4; j++) cpa16(sB + dOffB[j], bSrc[j] + (size_t)kt * (64 * FFN2));
        }
        cp_commit();
    };

    issue(0); issue(1);
    for (int kt = 0; kt < 32; kt++) {
        cp_wait1();
        __syncthreads();
        issue(kt + 2);
        const uint32_t sa = sb + (uint32_t)(kt % 3) * STG;
        const uint32_t sB = sa + TILE_B;
        #pragma unroll
        for (int ks = 0; ks < 4; ks++) {
            uint32_t a[2][4];
            #pragma unroll
            for (int mt = 0; mt < 2; mt++)
                ldsm4(a[mt][0], a[mt][1], a[mt][2], a[mt][3],
                      sa + aRow[mt] + ((((uint32_t)(2 * ks) + hiA) ^ aS[mt]) << 4));
            #pragma unroll
            for (int nq = 0; nq < 4; nq++) {
                uint32_t b0, b1, b2, b3;
                ldsm4t(b0, b1, b2, b3, sB + (uint32_t)(ks * 4096) + rowB + swB[nq]);
                #pragma unroll
                for (int mt = 0; mt < 2; mt++) {
                    mma16(acc[mt][nq * 2 + 0], a[mt], b0, b1);
                    mma16(acc[mt][nq * 2 + 1], a[mt], b2, b3);
                }
            }
        }
    }

    // epilogue: frags 0..3 = a-cols, 4..7 = matching b-cols
    const int lg = lane >> 2, lt = lane & 3;
    __half* actBase = g_act + ((size_t)(e * TOK_E + mtile * 128)) * FFN + n0 + wn * 32;
    #pragma unroll
    for (int mt = 0; mt < 2; mt++) {
        #pragma unroll
        for (int j = 0; j < 4; j++) {
            const int r = wm * 32 + mt * 16 + lg;
            const int c = 8 * j + 2 * lt;
            const float* pa = acc[mt][j];
            const float* pb = acc[mt][4 + j];
            __half2 v0 = __floats2half2_rn(silu(pa[0]) * pb[0], silu(pa[1]) * pb[1]);
            __half2 v1 = __floats2half2_rn(silu(pa[2]) * pb[2], silu(pa[3]) * pb[3]);
            *reinterpret_cast<__half2*>(actBase + (size_t)r * FFN + c)       = v0;
            *reinterpret_cast<__half2*>(actBase + (size_t)(r + 8) * FFN + c) = v1;
        }
    }
}

// ===========================================================================
// GEMM2: block 128m x 128n, B stage [k][n] native W2 layout.
// ===========================================================================
__global__ __launch_bounds__(256, 2)
void gemm2_kernel(float* __restrict__ out) {
    const int e = blockIdx.z, mtile = blockIdx.y, ntile = blockIdx.x;
    const int tid = threadIdx.x, warp = tid >> 5, lane = tid & 31;
    const int wm = warp >> 1, wn = warp & 1;
    extern __shared__ char smem[];
    const uint32_t sb = s2u(smem);
    const int n0 = ntile * 128;

    const int pr = tid >> 3, kc = tid & 7;
    const uint32_t swcA = (uint32_t)((kc ^ (pr & 7)) << 4);
    uint32_t dOffA[4];
    const __half* aSrc[4];
    {
        const __half* ae = g_act + ((size_t)(e * TOK_E + mtile * 128)) * FFN + kc * 8;
        #pragma unroll
        for (int i = 0; i < 4; i++) {
            dOffA[i] = (uint32_t)((pr + 32 * i) * 128) + swcA;
            aSrc[i]  = ae + (size_t)(pr + 32 * i) * FFN;
        }
    }

    const int rB = tid >> 3, cB = tid & 7;
    uint32_t dOffB[4];
    const __half* bSrc[4];
    {
        const __half* w2e = g_W2h + (size_t)e * FFN * HID;
        #pragma unroll
        for (int j = 0; j < 4; j++) {
            const int row = rB + (j >> 1) * 32;
            const int ch  = cB + (j & 1) * 8;
            dOffB[j] = (uint32_t)(row * 256 + ((ch ^ (rB & 7)) << 4));
            bSrc[j]  = w2e + (size_t)row * HID + n0 + ch * 8;
        }
    }

    const uint32_t hiA = lane >> 4;
    uint32_t aRow[2], aS[2];
    #pragma unroll
    for (int mt = 0; mt < 2; mt++) {
        const int r = wm * 32 + mt * 16 + (lane & 15);
        aRow[mt] = (uint32_t)(r * 128); aS[mt] = (uint32_t)(r & 7);
    }
    const uint32_t rowB = (uint32_t)((((lane >> 3) & 1) * 8 + (lane & 7)) * 256);
    uint32_t swB[4];
    #pragma unroll
    for (int nq = 0; nq < 4; nq++)
        swB[nq] = (uint32_t)((((wn * 8 + nq * 2 + (lane >> 4)) ^ (lane & 7))) << 4);

    float acc[2][8][4] = {};

    auto issue = [&](int kt) {
        if (kt < 22) {
            const uint32_t s  = sb + (uint32_t)(kt % 3) * STG;
            const uint32_t sB = s + TILE_B;
            #pragma unroll
            for (int i = 0; i < 4; i++) cpa16(s  + dOffA[i], aSrc[i] + (size_t)kt * 64);
            #pragma unroll
            for (int j = 0; j < 4; j++) cpa16(sB + dOffB[j], bSrc[j] + (size_t)kt * (64 * HID));
        }
        cp_commit();
    };

    issue(0); issue(1);
    for (int kt = 0; kt < 22; kt++) {
        cp_wait1();
        __syncthreads();
        issue(kt + 2);
        const uint32_t sa = sb + (uint32_t)(kt % 3) * STG;
        const uint32_t sB = sa + TILE_B;
        #pragma unroll
        for (int ks = 0; ks < 4; ks++) {
            uint32_t a[2][4];
            #pragma unroll
            for (int mt = 0; mt < 2; mt++)
                ldsm4(a[mt][0], a[mt][1], a[mt][2], a[mt][3],
                      sa + aRow[mt] + ((((uint32_t)(2 * ks) + hiA) ^ aS[mt]) << 4));
            #pragma unroll
            for (int nq = 0; nq < 4; nq++) {
                uint32_t b0, b1, b2, b3;
                ldsm4t(b0, b1, b2, b3, sB + (uint32_t)(ks * 4096) + rowB + swB[nq]);
                #pragma unroll
                for (int mt = 0; mt < 2; mt++) {
                    mma16(acc[mt][nq * 2 + 0], a[mt], b0, b1);
                    mma16(acc[mt][nq * 2 + 1], a[mt], b2, b3);
                }
            }
        }
    }

    const int lg = lane >> 2, lt = lane & 3;
    float* outBase = out + ((size_t)(e * TOK_E + mtile * 128)) * HID + n0 + wn * 64;
    #pragma unroll
    for (int mt = 0; mt < 2; mt++) {
        #pragma unroll
        for (int j = 0; j < 8; j++) {
            const int r = wm * 32 + mt * 16 + lg;
            const int c = 8 * j + 2 * lt;
            const float* d = acc[mt][j];
            *reinterpret_cast<float2*>(outBase + (size_t)r * HID + c)       = make_float2(d[0], d[1]);
            *reinterpret_cast<float2*>(outBase + (size_t)(r + 8) * HID + c) = make_float2(d[2], d[3]);
        }
    }
}

// ===========================================================================
// Launch
// ===========================================================================
extern "C" void kernel_launch(void* const* d_in, const int* in_sizes, int n_in,
                              void* d_out, int out_size) {
    const float* X  = (const float*)d_in[0];
    const float* W1 = (const float*)d_in[2];
    const float* W2 = (const float*)d_in[3];
    float* out = (float*)d_out;

    __half* xh;  cudaGetSymbolAddress((void**)&xh,  g_Xh);
    __half* w1h; cudaGetSymbolAddress((void**)&w1h, g_W1h);

    cudaFuncSetAttribute(gemm1_kernel, cudaFuncAttributeMaxDynamicSharedMemorySize, SMEM_TOTAL);
    cudaFuncSetAttribute(gemm2_kernel, cudaFuncAttributeMaxDynamicSharedMemorySize, SMEM_TOTAL);

    // prepass: X and W1 (critical path); W2 converts inside gemm1's grid
    cvt_kernel<<<2048, 256>>>(X,  xh,  (size_t)TOK_E * NEXPERTS * HID / 4);
    cvt_kernel<<<2048, 256>>>(W1, w1h, (size_t)NEXPERTS * HID * FFN2 / 4);

    // gemm1: x = 0..21 GEMM tiles, x = 22 -> 64 W2-convert CTAs
    gemm1_kernel<<<dim3(23, TOK_E / 128, NEXPERTS), 256, SMEM_TOTAL>>>(W2);
    gemm2_kernel<<<dim3(HID / 128, TOK_E / 128, NEXPERTS), 256, SMEM_TOTAL>>>(out);
}

// round 8
// speedup vs baseline: 3.0025x; 1.0014x over previous
#include <cuda_runtime.h>
#include <cuda_fp16.h>
#include <cstdint>

// ---------------------------------------------------------------------------
// Experts MoE, fp16 mma.sync m16n8k16, fp32 accum (compute_103-safe).
// Round 8: register-pipelined fragments — A frags for the full BK=64 iter
// hoisted (8x LDSM.x4), B frags ping-ponged one step ahead, so HMMA never
// waits on a same-step LDSM. 2 CTAs/SM, 128x128 block, 32x64 warp tile,
// XOR-swizzled smem, 3-stage cp.async. W2 cvt folded into gemm1's grid.
// ---------------------------------------------------------------------------

#define NEXPERTS 8
#define TOK_E    2048
#define HID      2048
#define FFN      1408
#define FFN2     2816

#define TILE_B 16384
#define STG    (2 * TILE_B)             // 32768
#define SMEM_TOTAL (3 * STG)            // 98304

#define W2_F4_PER_CTA 90112             // (8*1408*2048/4)/64

__device__ __half g_Xh [(size_t)TOK_E * NEXPERTS * HID];
__device__ __half g_W1h[(size_t)NEXPERTS * HID * FFN2];    // [e][k][n] fp16
__device__ __half g_W2h[(size_t)NEXPERTS * FFN * HID];     // [e][k][n] fp16
__device__ __half g_act[(size_t)NEXPERTS * TOK_E * FFN];

__device__ __forceinline__ uint32_t s2u(const void* p) {
    uint32_t a;
    asm("{ .reg .u64 t; cvta.to.shared.u64 t, %1; cvt.u32.u64 %0, t; }" : "=r"(a) : "l"(p));
    return a;
}
__device__ __forceinline__ void cpa16(uint32_t s, const void* g) {
    asm volatile("cp.async.cg.shared.global [%0], [%1], 16;" :: "r"(s), "l"(g));
}
__device__ __forceinline__ void cp_commit() {
    asm volatile("cp.async.commit_group;" ::: "memory");
}
__device__ __forceinline__ void cp_wait1() {
    asm volatile("cp.async.wait_group 1;" ::: "memory");
}
__device__ __forceinline__ void ldsm4(uint32_t* r, uint32_t addr) {
    asm volatile("ldmatrix.sync.aligned.m8n8.x4.shared.b16 {%0,%1,%2,%3}, [%4];"
                 : "=r"(r[0]), "=r"(r[1]), "=r"(r[2]), "=r"(r[3]) : "r"(addr));
}
__device__ __forceinline__ void ldsm4t(uint32_t* r, uint32_t addr) {
    asm volatile("ldmatrix.sync.aligned.m8n8.x4.trans.shared.b16 {%0,%1,%2,%3}, [%4];"
                 : "=r"(r[0]), "=r"(r[1]), "=r"(r[2]), "=r"(r[3]) : "r"(addr));
}
__device__ __forceinline__ void mma16(float d[4], const uint32_t a[4], uint32_t b0, uint32_t b1) {
    asm volatile(
        "mma.sync.aligned.m16n8k16.row.col.f32.f16.f16.f32 "
        "{%0,%1,%2,%3}, {%4,%5,%6,%7}, {%8,%9}, {%0,%1,%2,%3};\n"
        : "+f"(d[0]), "+f"(d[1]), "+f"(d[2]), "+f"(d[3])
        : "r"(a[0]), "r"(a[1]), "r"(a[2]), "r"(a[3]), "r"(b0), "r"(b1));
}
__device__ __forceinline__ float silu(float x) { return x / (1.0f + __expf(-x)); }

__device__ __forceinline__ uint2 cvt4h(float4 v) {
    __half2 h0 = __floats2half2_rn(v.x, v.y);
    __half2 h1 = __floats2half2_rn(v.z, v.w);
    uint2 u;
    u.x = *reinterpret_cast<uint32_t*>(&h0);
    u.y = *reinterpret_cast<uint32_t*>(&h1);
    return u;
}

// ===========================================================================
// Streaming f32 -> fp16 convert
// ===========================================================================
__global__ __launch_bounds__(256)
void cvt_kernel(const float* __restrict__ src, __half* __restrict__ dst, size_t n4) {
    const float4* s4 = reinterpret_cast<const float4*>(src);
    uint2* d4 = reinterpret_cast<uint2*>(dst);
    for (size_t i = (size_t)blockIdx.x * blockDim.x + threadIdx.x; i < n4;
         i += (size_t)gridDim.x * blockDim.x)
        d4[i] = cvt4h(s4[i]);
}

// ===========================================================================
// Pipelined compute for one BK=64 stage (shared by both GEMMs).
// acc[2][8][4], A hoisted for all 4 ks, B ping-ponged one LDSM ahead.
// ===========================================================================
#define COMPUTE_STAGE(sa, sB)                                                   \
    {                                                                           \
        uint32_t afr[4][2][4];                                                  \
        _Pragma("unroll")                                                       \
        for (int ks = 0; ks < 4; ks++)                                          \
            _Pragma("unroll")                                                   \
            for (int mt = 0; mt < 2; mt++)                                      \
                ldsm4(afr[ks][mt],                                              \
                      (sa) + aRow[mt] + ((((uint32_t)(2 * ks) + hiA) ^ aS[mt]) << 4)); \
        uint32_t bf[2][4];                                                      \
        ldsm4t(bf[0], (sB) + rowB + swB[0]);                                    \
        _Pragma("unroll")                                                       \
        for (int s = 0; s < 16; s++) {                                          \
            const int ks = s >> 2, nq = s & 3;                                  \
            const int cur = s & 1, nxt = cur ^ 1;                               \
            if (s < 15) {                                                       \
                const int s1 = s + 1;                                           \
                ldsm4t(bf[nxt], (sB) + (uint32_t)((s1 >> 2) * 4096) + rowB + swB[s1 & 3]); \
            }                                                                   \
            mma16(acc[0][nq * 2 + 0], afr[ks][0], bf[cur][0], bf[cur][1]);      \
            mma16(acc[1][nq * 2 + 0], afr[ks][1], bf[cur][0], bf[cur][1]);      \
            mma16(acc[0][nq * 2 + 1], afr[ks][0], bf[cur][2], bf[cur][3]);      \
            mma16(acc[1][nq * 2 + 1], afr[ks][1], bf[cur][2], bf[cur][3]);      \
        }                                                                       \
    }

// ===========================================================================
// GEMM1 + swiglu. ntile 0..21 = GEMM (128m x 64 act-cols); ntile 22 = W2 cvt.
// ===========================================================================
__global__ __launch_bounds__(256, 2)
void gemm1_kernel(const float* __restrict__ W2src) {
    if (blockIdx.x == 22) {
        if (blockIdx.y >= 8) return;
        const size_t cid = (size_t)blockIdx.z * 8 + blockIdx.y;
        const float4* s4 = reinterpret_cast<const float4*>(W2src) + cid * W2_F4_PER_CTA;
        uint2* d4 = reinterpret_cast<uint2*>(g_W2h) + cid * W2_F4_PER_CTA;
        #pragma unroll 4
        for (int i = threadIdx.x; i < W2_F4_PER_CTA; i += 256)
            d4[i] = cvt4h(s4[i]);
        return;
    }

    const int e = blockIdx.z, mtile = blockIdx.y, ntile = blockIdx.x;
    const int tid = threadIdx.x, warp = tid >> 5, lane = tid & 31;
    const int wm = warp >> 1, wn = warp & 1;
    extern __shared__ char smem[];
    const uint32_t sb = s2u(smem);
    const int n0 = ntile * 64;

    const int pr = tid >> 3, kc = tid & 7;
    const uint32_t swcA = (uint32_t)((kc ^ (pr & 7)) << 4);
    uint32_t dOffA[4];
    const __half* aSrc[4];
    {
        const __half* xe = g_Xh + ((size_t)(e * TOK_E + mtile * 128)) * HID + kc * 8;
        #pragma unroll
        for (int i = 0; i < 4; i++) {
            dOffA[i] = (uint32_t)((pr + 32 * i) * 128) + swcA;
            aSrc[i]  = xe + (size_t)(pr + 32 * i) * HID;
        }
    }

    const int rB = tid >> 3, cB = tid & 7;
    uint32_t dOffB[4];
    const __half* bSrc[4];
    {
        const __half* w1e = g_W1h + (size_t)e * HID * FFN2;
        #pragma unroll
        for (int j = 0; j < 4; j++) {
            const int row = rB + (j >> 1) * 32;
            const int ch  = cB + (j & 1) * 8;
            const int g   = ch >> 2;
            const int col = n0 + (g >> 1) * 32 + (ch & 3) * 8 + ((g & 1) ? FFN : 0);
            dOffB[j] = (uint32_t)(row * 256 + ((ch ^ (rB & 7)) << 4));
            bSrc[j]  = w1e + (size_t)row * FFN2 + col;
        }
    }

    const uint32_t hiA = lane >> 4;
    uint32_t aRow[2], aS[2];
    #pragma unroll
    for (int mt = 0; mt < 2; mt++) {
        const int r = wm * 32 + mt * 16 + (lane & 15);
        aRow[mt] = (uint32_t)(r * 128); aS[mt] = (uint32_t)(r & 7);
    }
    const uint32_t rowB = (uint32_t)((((lane >> 3) & 1) * 8 + (lane & 7)) * 256);
    uint32_t swB[4];
    #pragma unroll
    for (int nq = 0; nq < 4; nq++)
        swB[nq] = (uint32_t)((((wn * 8 + nq * 2 + (lane >> 4)) ^ (lane & 7))) << 4);

    float acc[2][8][4] = {};

    auto issue = [&](int kt) {
        if (kt < 32) {
            const uint32_t s  = sb + (uint32_t)(kt % 3) * STG;
            const uint32_t sB = s + TILE_B;
            #pragma unroll
            for (int i = 0; i < 4; i++) cpa16(s  + dOffA[i], aSrc[i] + (size_t)kt * 64);
            #pragma unroll
            for (int j = 0; j < 4; j++) cpa16(sB + dOffB[j], bSrc[j] + (size_t)kt * (64 * FFN2));
        }
        cp_commit();
    };

    issue(0); issue(1);
    for (int kt = 0; kt < 32; kt++) {
        cp_wait1();
        __syncthreads();
        issue(kt + 2);
        const uint32_t sa = sb + (uint32_t)(kt % 3) * STG;
        const uint32_t sB = sa + TILE_B;
        COMPUTE_STAGE(sa, sB)
    }

    const int lg = lane >> 2, lt = lane & 3;
    __half* actBase = g_act + ((size_t)(e * TOK_E + mtile * 128)) * FFN + n0 + wn * 32;
    #pragma unroll
    for (int mt = 0; mt < 2; mt++) {
        #pragma unroll
        for (int j = 0; j < 4; j++) {
            const int r = wm * 32 + mt * 16 + lg;
            const int c = 8 * j + 2 * lt;
            const float* pa = acc[mt][j];
            const float* pb = acc[mt][4 + j];
            __half2 v0 = __floats2half2_rn(silu(pa[0]) * pb[0], silu(pa[1]) * pb[1]);
            __half2 v1 = __floats2half2_rn(silu(pa[2]) * pb[2], silu(pa[3]) * pb[3]);
            *reinterpret_cast<__half2*>(actBase + (size_t)r * FFN + c)       = v0;
            *reinterpret_cast<__half2*>(actBase + (size_t)(r + 8) * FFN + c) = v1;
        }
    }
}

// ===========================================================================
// GEMM2: block 128m x 128n
// ===========================================================================
__global__ __launch_bounds__(256, 2)
void gemm2_kernel(float* __restrict__ out) {
    const int e = blockIdx.z, mtile = blockIdx.y, ntile = blockIdx.x;
    const int tid = threadIdx.x, warp = tid >> 5, lane = tid & 31;
    const int wm = warp >> 1, wn = warp & 1;
    extern __shared__ char smem[];
    const uint32_t sb = s2u(smem);
    const int n0 = ntile * 128;

    const int pr = tid >> 3, kc = tid & 7;
    const uint32_t swcA = (uint32_t)((kc ^ (pr & 7)) << 4);
    uint32_t dOffA[4];
    const __half* aSrc[4];
    {
        const __half* ae = g_act + ((size_t)(e * TOK_E + mtile * 128)) * FFN + kc * 8;
        #pragma unroll
        for (int i = 0; i < 4; i++) {
            dOffA[i] = (uint32_t)((pr + 32 * i) * 128) + swcA;
            aSrc[i]  = ae + (size_t)(pr + 32 * i) * FFN;
        }
    }

    const int rB = tid >> 3, cB = tid & 7;
    uint32_t dOffB[4];
    const __half* bSrc[4];
    {
        const __half* w2e = g_W2h + (size_t)e * FFN * HID;
        #pragma unroll
        for (int j = 0; j < 4; j++) {
            const int row = rB + (j >> 1) * 32;
            const int ch  = cB + (j & 1) * 8;
            dOffB[j] = (uint32_t)(row * 256 + ((ch ^ (rB & 7)) << 4));
            bSrc[j]  = w2e + (size_t)row * HID + n0 + ch * 8;
        }
    }

    const uint32_t hiA = lane >> 4;
    uint32_t aRow[2], aS[2];
    #pragma unroll
    for (int mt = 0; mt < 2; mt++) {
        const int r = wm * 32 + mt * 16 + (lane & 15);
        aRow[mt] = (uint32_t)(r * 128); aS[mt] = (uint32_t)(r & 7);
    }
    const uint32_t rowB = (uint32_t)((((lane >> 3) & 1) * 8 + (lane & 7)) * 256);
    uint32_t swB[4];
    #pragma unroll
    for (int nq = 0; nq < 4; nq++)
        swB[nq] = (uint32_t)((((wn * 8 + nq * 2 + (lane >> 4)) ^ (lane & 7))) << 4);

    float acc[2][8][4] = {};

    auto issue = [&](int kt) {
        if (kt < 22) {
            const uint32_t s  = sb + (uint32_t)(kt % 3) * STG;
            const uint32_t sB = s + TILE_B;
            #pragma unroll
            for (int i = 0; i < 4; i++) cpa16(s  + dOffA[i], aSrc[i] + (size_t)kt * 64);
            #pragma unroll
            for (int j = 0; j < 4; j++) cpa16(sB + dOffB[j], bSrc[j] + (size_t)kt * (64 * HID));
        }
        cp_commit();
    };

    issue(0); issue(1);
    for (int kt = 0; kt < 22; kt++) {
        cp_wait1();
        __syncthreads();
        issue(kt + 2);
        const uint32_t sa = sb + (uint32_t)(kt % 3) * STG;
        const uint32_t sB = sa + TILE_B;
        COMPUTE_STAGE(sa, sB)
    }

    const int lg = lane >> 2, lt = lane & 3;
    float* outBase = out + ((size_t)(e * TOK_E + mtile * 128)) * HID + n0 + wn * 64;
    #pragma unroll
    for (int mt = 0; mt < 2; mt++) {
        #pragma unroll
        for (int j = 0; j < 8; j++) {
            const int r = wm * 32 + mt * 16 + lg;
            const int c = 8 * j + 2 * lt;
            const float* d = acc[mt][j];
            *reinterpret_cast<float2*>(outBase + (size_t)r * HID + c)       = make_float2(d[0], d[1]);
            *reinterpret_cast<float2*>(outBase + (size_t)(r + 8) * HID + c) = make_float2(d[2], d[3]);
        }
    }
}

// ===========================================================================
// Launch
// ===========================================================================
extern "C" void kernel_launch(void* const* d_in, const int* in_sizes, int n_in,
                              void* d_out, int out_size) {
    const float* X  = (const float*)d_in[0];
    const float* W1 = (const float*)d_in[2];
    const float* W2 = (const float*)d_in[3];
    float* out = (float*)d_out;

    __half* xh;  cudaGetSymbolAddress((void**)&xh,  g_Xh);
    __half* w1h; cudaGetSymbolAddress((void**)&w1h, g_W1h);

    cudaFuncSetAttribute(gemm1_kernel, cudaFuncAttributeMaxDynamicSharedMemorySize, SMEM_TOTAL);
    cudaFuncSetAttribute(gemm2_kernel, cudaFuncAttributeMaxDynamicSharedMemorySize, SMEM_TOTAL);

    cvt_kernel<<<2048, 256>>>(X,  xh,  (size_t)TOK_E * NEXPERTS * HID / 4);
    cvt_kernel<<<2048, 256>>>(W1, w1h, (size_t)NEXPERTS * HID * FFN2 / 4);

    gemm1_kernel<<<dim3(23, TOK_E / 128, NEXPERTS), 256, SMEM_TOTAL>>>(W2);
    gemm2_kernel<<<dim3(HID / 128, TOK_E / 128, NEXPERTS), 256, SMEM_TOTAL>>>(out);
}